// round 1
// baseline (speedup 1.0000x reference)
#include <cuda_runtime.h>
#include <math.h>

// Problem constants
#define BB 256
#define NN 50
#define FF 6144
#define HH 4
#define OO 64
#define NT (HH*OO)          // 256 output cols of the big GEMM
#define MT (BB*NN)          // 12800 rows

// Scratch: Wh[m][c], m = b*50+n, c = h*64+o  (13.1 MB)
__device__ float g_Wh[(size_t)MT * NT];

// ---------------------------------------------------------------------------
// Kernel A: Wh = h @ W'   (M=12800, K=6144, N=256)
// W'[f][c] = W[c>>6][f][c&63]   (W is (H,F,O) contiguous)
// Tiling: BM=64, BN=256 (full width -> h read exactly once), BK=16.
// 256 threads, each computes an 8x8 microtile.
// ---------------------------------------------------------------------------
__global__ __launch_bounds__(256, 2)
void gemm_kernel(const float* __restrict__ hmat, const float* __restrict__ W)
{
    const int BM = 64, BN = 256, BK = 16;
    __shared__ float As[BK][BM];   // transposed A tile
    __shared__ float Bs[BK][BN];

    const int tid  = threadIdx.x;
    const int row0 = blockIdx.x * BM;
    const int tr   = tid >> 5;          // 0..7   (row group)
    const int tc   = tid & 31;          // 0..31  (col group)

    float acc[8][8];
#pragma unroll
    for (int i = 0; i < 8; i++)
#pragma unroll
        for (int j = 0; j < 8; j++) acc[i][j] = 0.f;

    // A load: 1 float4/thread.  row a_r = tid>>2, k-offset a_k = (tid&3)*4
    const int a_r = tid >> 2;
    const int a_k = (tid & 3) * 4;
    const float* Aptr = hmat + (size_t)(row0 + a_r) * FF + a_k;

    const int nKT = FF / BK;            // 384
    for (int kt = 0; kt < nKT; kt++) {
        const int k0 = kt * BK;

        // global loads into registers first (overlap with previous compute)
        float4 av = *(const float4*)(Aptr + k0);
        float4 bv[4];
#pragma unroll
        for (int i = 0; i < 4; i++) {
            int p  = tid + i * 256;     // 0..1023
            int r  = p >> 6;            // 0..15 (k within tile)
            int c  = (p & 63) * 4;      // 0..252
            int hh = c >> 6;
            int oo = c & 63;
            bv[i] = *(const float4*)(W + (size_t)hh * FF * OO + (size_t)(k0 + r) * OO + oo);
        }

        __syncthreads();
        As[a_k + 0][a_r] = av.x;
        As[a_k + 1][a_r] = av.y;
        As[a_k + 2][a_r] = av.z;
        As[a_k + 3][a_r] = av.w;
#pragma unroll
        for (int i = 0; i < 4; i++) {
            int p = tid + i * 256;
            int r = p >> 6;
            int c = (p & 63) * 4;
            *(float4*)&Bs[r][c] = bv[i];
        }
        __syncthreads();

#pragma unroll
        for (int k = 0; k < BK; k++) {
            float ra[8], rb[8];
#pragma unroll
            for (int i = 0; i < 8; i++) ra[i] = As[k][tr * 8 + i];
#pragma unroll
            for (int j = 0; j < 8; j++) rb[j] = Bs[k][tc * 8 + j];
#pragma unroll
            for (int i = 0; i < 8; i++)
#pragma unroll
                for (int j = 0; j < 8; j++)
                    acc[i][j] = fmaf(ra[i], rb[j], acc[i][j]);
        }
    }

    // epilogue: g_Wh[m*256 + c]
#pragma unroll
    for (int i = 0; i < 8; i++) {
        int m = row0 + tr * 8 + i;
#pragma unroll
        for (int j = 0; j < 8; j += 4) {
            int c = tc * 8 + j;
            float4 v = make_float4(acc[i][j], acc[i][j + 1], acc[i][j + 2], acc[i][j + 3]);
            *(float4*)&g_Wh[(size_t)m * NT + c] = v;
        }
    }
}

// ---------------------------------------------------------------------------
// Kernel B: per-batch fused Gumbel adjacency + GAT attention + ELU epilogue.
// One block per b (256 blocks, 256 threads). Loops over the 4 heads.
// ---------------------------------------------------------------------------
__global__ __launch_bounds__(256)
void attn_kernel(const float* __restrict__ probs,
                 const float* __restrict__ u,
                 const float* __restrict__ a,
                 float* __restrict__ out)
{
    __shared__ float sWh[NN][OO];       // 12.8 KB
    __shared__ float sA2[NN][OO];       // 12.8 KB
    __shared__ float sE[NN][NN];        // 10 KB (s2 then att, in place)
    __shared__ float sS1[NN];
    __shared__ unsigned char sAdj[NN * NN];

    const int b    = blockIdx.x;
    const int tid  = threadIdx.x;
    const int lane = tid & 31;
    const int wid  = tid >> 5;

    // ---- adjacency (shared across heads) ----
    for (int idx = tid; idx < NN * NN; idx += 256) {
        float p  = probs[(size_t)b * (NN * NN) + idx];
        float u0 = u[((size_t)b * (NN * NN) + idx) * 2 + 0];
        float u1 = u[((size_t)b * (NN * NN) + idx) * 2 + 1];
        float x0 = p, x1 = 1.f - p;
        float mx = fmaxf(x0, x1);
        float e0 = expf(x0 - mx), e1 = expf(x1 - mx);
        float inv = 1.f / (e0 + e1);
        float p0 = e0 * inv, p1 = e1 * inv;
        float l0 = logf(p0 + 1e-5f);
        float l1 = logf(p1 + 1e-5f);
        float g0 = -logf(-logf(u0 + 1e-10f) + 1e-10f);
        float g1 = -logf(-logf(u1 + 1e-10f) + 1e-10f);
        // argmax (first max wins) of (logits+g)/TAU over {0,1} -> channel 0 iff >=
        sAdj[idx] = (l0 + g0 >= l1 + g1) ? 1 : 0;
    }

    for (int h = 0; h < HH; h++) {
        __syncthreads();  // protect sWh/sE reuse across iterations (and sAdj on h=0)

        // ---- load Wh tile and a2 (both 50x64) ----
        for (int idx = tid; idx < NN * OO / 4; idx += 256) {
            int n_ = idx >> 4;            // 16 float4 per row
            int o4 = (idx & 15) * 4;
            *(float4*)&sWh[n_][o4] =
                *(const float4*)&g_Wh[(size_t)(b * NN + n_) * NT + h * OO + o4];
            *(float4*)&sA2[n_][o4] =
                *(const float4*)&a[(size_t)(h * NN + n_) * (2 * OO) + OO + o4];
        }
        __syncthreads();

        // ---- s1[n] = <Wh[n], a1[n]>  (warp per row) ----
        for (int n_ = wid; n_ < NN; n_ += 8) {
            float a1v0 = a[(size_t)(h * NN + n_) * (2 * OO) + lane];
            float a1v1 = a[(size_t)(h * NN + n_) * (2 * OO) + lane + 32];
            float v = sWh[n_][lane] * a1v0 + sWh[n_][lane + 32] * a1v1;
#pragma unroll
            for (int off = 16; off; off >>= 1) v += __shfl_xor_sync(0xffffffffu, v, off);
            if (lane == 0) sS1[n_] = v;
        }

        // ---- s2[n][m] = <a2[n], Wh[m]> ----
        for (int idx = tid; idx < NN * NN; idx += 256) {
            int n_ = idx / NN, m_ = idx % NN;
            float v = 0.f;
#pragma unroll 16
            for (int o = 0; o < OO; o++) v = fmaf(sA2[n_][o], sWh[m_][o], v);
            sE[n_][m_] = v;
        }
        __syncthreads();

        // ---- leaky + mask + row softmax (warp per row, 2 elems/lane) ----
        for (int n_ = wid; n_ < NN; n_ += 8) {
            float s1v = sS1[n_];
            int m0 = lane, m1 = lane + 32;
            float t0 = s1v + sE[n_][m0];
            t0 = (t0 >= 0.f) ? t0 : 0.2f * t0;
            float v0 = sAdj[n_ * NN + m0] ? t0 : -9e15f;
            float v1 = -9e15f;
            if (m1 < NN) {
                float t1 = s1v + sE[n_][m1];
                t1 = (t1 >= 0.f) ? t1 : 0.2f * t1;
                v1 = sAdj[n_ * NN + m1] ? t1 : -9e15f;
            }
            float mx = fmaxf(v0, v1);
#pragma unroll
            for (int off = 16; off; off >>= 1)
                mx = fmaxf(mx, __shfl_xor_sync(0xffffffffu, mx, off));
            float e0_ = expf(v0 - mx);
            float e1_ = (m1 < NN) ? expf(v1 - mx) : 0.f;
            float sum = e0_ + e1_;
#pragma unroll
            for (int off = 16; off; off >>= 1)
                sum += __shfl_xor_sync(0xffffffffu, sum, off);
            float inv = 1.f / sum;
            sE[n_][m0] = e0_ * inv;
            if (m1 < NN) sE[n_][m1] = e1_ * inv;
        }
        __syncthreads();

        // ---- h_prime + ELU epilogue ----
        int o = tid & 63;
        for (int n_ = tid >> 6; n_ < NN; n_ += 4) {
            float v = 0.f;
#pragma unroll 10
            for (int m_ = 0; m_ < NN; m_++)
                v = fmaf(sE[n_][m_], sWh[m_][o], v);
            v += 0.3f * sWh[n_][o];
            v = (v > 0.f) ? v : expm1f(v);
            out[(size_t)(b * NN + n_) * NT + h * OO + o] = v;
        }
    }
}

// ---------------------------------------------------------------------------
extern "C" void kernel_launch(void* const* d_in, const int* in_sizes, int n_in,
                              void* d_out, int out_size)
{
    const float* h_    = (const float*)d_in[0];  // (B, N, F)
    const float* probs = (const float*)d_in[1];  // (B, N*N)
    const float* u_    = (const float*)d_in[2];  // (B, N*N, 2)
    const float* W_    = (const float*)d_in[3];  // (H, F, O)
    const float* a_    = (const float*)d_in[4];  // (H, N, 2*O)
    float* out = (float*)d_out;

    gemm_kernel<<<MT / 64, 256>>>(h_, W_);
    attn_kernel<<<BB, 256>>>(probs, u_, a_, out);
}

// round 2
// speedup vs baseline: 2.6617x; 2.6617x over previous
#include <cuda_runtime.h>
#include <math.h>
#include <stdint.h>

// Problem constants
#define BB 256
#define NN 50
#define FF 6144
#define HH 4
#define OO 64
#define NT (HH*OO)          // 256 output cols of the big GEMM
#define MT (BB*NN)          // 12800 rows

// GEMM tiling
#define BM 128
#define BN 128
#define BK 16
#define PAD 8               // smem row stride BM+8 = 136 -> conflict-free frag loads

// Scratch: Wh[m][c], m = b*50+n, c = h*64+o  (13.1 MB)
__device__ float g_Wh[(size_t)MT * NT];

__device__ __forceinline__ unsigned f2tf32(float x) {
    unsigned r;
    asm("cvt.rna.tf32.f32 %0, %1;" : "=r"(r) : "f"(x));
    return r;
}

__device__ __forceinline__ void mma_tf32(float c[4],
                                         const unsigned a[4],
                                         const unsigned b[2]) {
    asm volatile(
        "mma.sync.aligned.m16n8k8.row.col.f32.tf32.tf32.f32 "
        "{%0,%1,%2,%3}, {%4,%5,%6,%7}, {%8,%9}, {%0,%1,%2,%3};"
        : "+f"(c[0]), "+f"(c[1]), "+f"(c[2]), "+f"(c[3])
        : "r"(a[0]), "r"(a[1]), "r"(a[2]), "r"(a[3]),
          "r"(b[0]), "r"(b[1]));
}

// ---------------------------------------------------------------------------
// Kernel A: Wh = h @ W'   (M=12800, K=6144, N=256) via tf32 tensor cores.
// W'[f][c] = W[c>>6][f][c&63]   (W is (H,F,O) contiguous)
// Grid (100, 2): 128x128 CTA tiles. 256 threads = 8 warps, warp tile 32x64.
// ---------------------------------------------------------------------------
__global__ __launch_bounds__(256, 2)
void gemm_tc(const float* __restrict__ hmat, const float* __restrict__ W)
{
    __shared__ float As[2][BK][BM + PAD];   // tf32 bits, k-major (transposed)
    __shared__ float Bs[2][BK][BN + PAD];   // tf32 bits

    const int tid  = threadIdx.x;
    const int lane = tid & 31;
    const int wid  = tid >> 5;
    const int wm   = wid & 3;               // warp row 0..3 (32 rows each)
    const int wn   = wid >> 2;              // warp col 0..1 (64 cols each)
    const int row0 = blockIdx.x * BM;
    const int col0 = blockIdx.y * BN;

    float acc[2][8][4];
#pragma unroll
    for (int mt = 0; mt < 2; mt++)
#pragma unroll
        for (int nt = 0; nt < 8; nt++)
#pragma unroll
            for (int i = 0; i < 4; i++) acc[mt][nt][i] = 0.f;

    // staging register buffers
    float4 va[2], vb[2];

    // A: 128x16 tile = 512 float4. p -> row m = p>>2, kq = (p&3)*4
    // B: 16x128 tile = 512 float4. p -> row k = p>>5, n  = (p&31)*4
    const float* Abase = hmat + (size_t)row0 * FF;

#define LDG_TILE(k0)                                                          \
    {                                                                         \
        _Pragma("unroll")                                                     \
        for (int i = 0; i < 2; i++) {                                         \
            int p = tid + i * 256;                                            \
            int m = p >> 2, kq = (p & 3) * 4;                                 \
            va[i] = *(const float4*)(Abase + (size_t)m * FF + (k0) + kq);     \
        }                                                                     \
        _Pragma("unroll")                                                     \
        for (int i = 0; i < 2; i++) {                                         \
            int p = tid + i * 256;                                            \
            int k = p >> 5, n = (p & 31) * 4;                                 \
            int c = col0 + n;                                                 \
            int hh = c >> 6, oo = c & 63;                                     \
            vb[i] = *(const float4*)(W + (size_t)hh * FF * OO +               \
                                     (size_t)((k0) + k) * OO + oo);           \
        }                                                                     \
    }

#define STS_TILE(buf)                                                         \
    {                                                                         \
        _Pragma("unroll")                                                     \
        for (int i = 0; i < 2; i++) {                                         \
            int p = tid + i * 256;                                            \
            int m = p >> 2, kq = (p & 3) * 4;                                 \
            As[buf][kq + 0][m] = __uint_as_float(f2tf32(va[i].x));            \
            As[buf][kq + 1][m] = __uint_as_float(f2tf32(va[i].y));            \
            As[buf][kq + 2][m] = __uint_as_float(f2tf32(va[i].z));            \
            As[buf][kq + 3][m] = __uint_as_float(f2tf32(va[i].w));            \
        }                                                                     \
        _Pragma("unroll")                                                     \
        for (int i = 0; i < 2; i++) {                                         \
            int p = tid + i * 256;                                            \
            int k = p >> 5, n = (p & 31) * 4;                                 \
            Bs[buf][k][n + 0] = __uint_as_float(f2tf32(vb[i].x));             \
            Bs[buf][k][n + 1] = __uint_as_float(f2tf32(vb[i].y));             \
            Bs[buf][k][n + 2] = __uint_as_float(f2tf32(vb[i].z));             \
            Bs[buf][k][n + 3] = __uint_as_float(f2tf32(vb[i].w));             \
        }                                                                     \
    }

    // prologue: stage k-tile 0 into buffer 0
    LDG_TILE(0);
    STS_TILE(0);
    __syncthreads();

    const int nKT = FF / BK;    // 384
    for (int kt = 0; kt < nKT; kt++) {
        const int cur = kt & 1;

        if (kt + 1 < nKT) LDG_TILE((kt + 1) * BK);

        // compute on buffer `cur`
#pragma unroll
        for (int ks = 0; ks < 2; ks++) {
            const int kb = ks * 8;
            unsigned a[2][4], b[8][2];
            const int kA = kb + (lane & 3);
            const int mA = wm * 32 + (lane >> 2);
#pragma unroll
            for (int mt = 0; mt < 2; mt++) {
                int m = mA + mt * 16;
                a[mt][0] = __float_as_uint(As[cur][kA    ][m]);
                a[mt][1] = __float_as_uint(As[cur][kA    ][m + 8]);
                a[mt][2] = __float_as_uint(As[cur][kA + 4][m]);
                a[mt][3] = __float_as_uint(As[cur][kA + 4][m + 8]);
            }
            const int nB = wn * 64 + (lane >> 2);
#pragma unroll
            for (int nt = 0; nt < 8; nt++) {
                int n = nB + nt * 8;
                b[nt][0] = __float_as_uint(Bs[cur][kA    ][n]);
                b[nt][1] = __float_as_uint(Bs[cur][kA + 4][n]);
            }
#pragma unroll
            for (int mt = 0; mt < 2; mt++)
#pragma unroll
                for (int nt = 0; nt < 8; nt++)
                    mma_tf32(acc[mt][nt], a[mt], b[nt]);
        }

        if (kt + 1 < nKT) STS_TILE(cur ^ 1);
        __syncthreads();
    }

    // epilogue
#pragma unroll
    for (int mt = 0; mt < 2; mt++) {
        int r = row0 + wm * 32 + mt * 16 + (lane >> 2);
#pragma unroll
        for (int nt = 0; nt < 8; nt++) {
            int c = col0 + wn * 64 + nt * 8 + (lane & 3) * 2;
            *(float2*)&g_Wh[(size_t)r * NT + c] =
                make_float2(acc[mt][nt][0], acc[mt][nt][1]);
            *(float2*)&g_Wh[(size_t)(r + 8) * NT + c] =
                make_float2(acc[mt][nt][2], acc[mt][nt][3]);
        }
    }
#undef LDG_TILE
#undef STS_TILE
}

// ---------------------------------------------------------------------------
// Kernel B: fused Gumbel adjacency + GAT attention + ELU epilogue.
// One block per (b, h): grid (256, 4), 256 threads. Padded smem (no conflicts).
// ---------------------------------------------------------------------------
__global__ __launch_bounds__(256)
void attn_kernel(const float* __restrict__ probs,
                 const float* __restrict__ u,
                 const float* __restrict__ a,
                 float* __restrict__ out)
{
    __shared__ float sWh[NN][OO + 1];       // padded: conflict-free column reads
    __shared__ float sA2[NN][OO + 1];
    __shared__ float sE[NN][NN];            // s2 then att, in place
    __shared__ float sS1[NN];
    __shared__ unsigned char sAdj[NN * NN];

    const int b    = blockIdx.x;
    const int h    = blockIdx.y;
    const int tid  = threadIdx.x;
    const int lane = tid & 31;
    const int wid  = tid >> 5;

    // ---- adjacency (recomputed per head; MUFU-cheap) ----
    for (int idx = tid; idx < NN * NN; idx += 256) {
        float p  = probs[(size_t)b * (NN * NN) + idx];
        float u0 = u[((size_t)b * (NN * NN) + idx) * 2 + 0];
        float u1 = u[((size_t)b * (NN * NN) + idx) * 2 + 1];
        float x0 = p, x1 = 1.f - p;
        float mx = fmaxf(x0, x1);
        float e0 = expf(x0 - mx), e1 = expf(x1 - mx);
        float inv = 1.f / (e0 + e1);
        float l0 = logf(e0 * inv + 1e-5f);
        float l1 = logf(e1 * inv + 1e-5f);
        float g0 = -logf(-logf(u0 + 1e-10f) + 1e-10f);
        float g1 = -logf(-logf(u1 + 1e-10f) + 1e-10f);
        sAdj[idx] = (l0 + g0 >= l1 + g1) ? 1 : 0;
    }

    // ---- load Wh tile and a2 (both 50x64) ----
    for (int idx = tid; idx < NN * OO / 4; idx += 256) {
        int n_ = idx >> 4;                  // 16 float4 per row
        int o4 = (idx & 15) * 4;
        float4 w = *(const float4*)&g_Wh[(size_t)(b * NN + n_) * NT + h * OO + o4];
        float4 av = *(const float4*)&a[(size_t)(h * NN + n_) * (2 * OO) + OO + o4];
        sWh[n_][o4] = w.x; sWh[n_][o4 + 1] = w.y;
        sWh[n_][o4 + 2] = w.z; sWh[n_][o4 + 3] = w.w;
        sA2[n_][o4] = av.x; sA2[n_][o4 + 1] = av.y;
        sA2[n_][o4 + 2] = av.z; sA2[n_][o4 + 3] = av.w;
    }
    __syncthreads();

    // ---- s1[n] = <Wh[n], a1[n]>  (warp per row) ----
    for (int n_ = wid; n_ < NN; n_ += 8) {
        float a1v0 = a[(size_t)(h * NN + n_) * (2 * OO) + lane];
        float a1v1 = a[(size_t)(h * NN + n_) * (2 * OO) + lane + 32];
        float v = sWh[n_][lane] * a1v0 + sWh[n_][lane + 32] * a1v1;
#pragma unroll
        for (int off = 16; off; off >>= 1) v += __shfl_xor_sync(0xffffffffu, v, off);
        if (lane == 0) sS1[n_] = v;
    }

    // ---- s2[n][m] = <a2[n], Wh[m]> ----
    for (int idx = tid; idx < NN * NN; idx += 256) {
        int n_ = idx / NN, m_ = idx % NN;
        float v = 0.f;
#pragma unroll 16
        for (int o = 0; o < OO; o++) v = fmaf(sA2[n_][o], sWh[m_][o], v);
        sE[n_][m_] = v;
    }
    __syncthreads();

    // ---- leaky + mask + row softmax (warp per row, 2 elems/lane) ----
    for (int n_ = wid; n_ < NN; n_ += 8) {
        float s1v = sS1[n_];
        int m0 = lane, m1 = lane + 32;
        float t0 = s1v + sE[n_][m0];
        t0 = (t0 >= 0.f) ? t0 : 0.2f * t0;
        float v0 = sAdj[n_ * NN + m0] ? t0 : -9e15f;
        float v1 = -9e15f;
        if (m1 < NN) {
            float t1 = s1v + sE[n_][m1];
            t1 = (t1 >= 0.f) ? t1 : 0.2f * t1;
            v1 = sAdj[n_ * NN + m1] ? t1 : -9e15f;
        }
        float mx = fmaxf(v0, v1);
#pragma unroll
        for (int off = 16; off; off >>= 1)
            mx = fmaxf(mx, __shfl_xor_sync(0xffffffffu, mx, off));
        float e0_ = expf(v0 - mx);
        float e1_ = (m1 < NN) ? expf(v1 - mx) : 0.f;
        float sum = e0_ + e1_;
#pragma unroll
        for (int off = 16; off; off >>= 1)
            sum += __shfl_xor_sync(0xffffffffu, sum, off);
        float inv = 1.f / sum;
        sE[n_][m0] = e0_ * inv;
        if (m1 < NN) sE[n_][m1] = e1_ * inv;
    }
    __syncthreads();

    // ---- h_prime + ELU epilogue ----
    int o = tid & 63;
    for (int n_ = tid >> 6; n_ < NN; n_ += 4) {
        float v = 0.f;
#pragma unroll 10
        for (int m_ = 0; m_ < NN; m_++)
            v = fmaf(sE[n_][m_], sWh[m_][o], v);
        v += 0.3f * sWh[n_][o];
        v = (v > 0.f) ? v : expm1f(v);
        out[(size_t)(b * NN + n_) * NT + h * OO + o] = v;
    }
}

// ---------------------------------------------------------------------------
extern "C" void kernel_launch(void* const* d_in, const int* in_sizes, int n_in,
                              void* d_out, int out_size)
{
    const float* h_    = (const float*)d_in[0];  // (B, N, F)
    const float* probs = (const float*)d_in[1];  // (B, N*N)
    const float* u_    = (const float*)d_in[2];  // (B, N*N, 2)
    const float* W_    = (const float*)d_in[3];  // (H, F, O)
    const float* a_    = (const float*)d_in[4];  // (H, N, 2*O)
    float* out = (float*)d_out;

    dim3 ggrid(MT / BM, NT / BN);                // (100, 2)
    gemm_tc<<<ggrid, 256>>>(h_, W_);

    dim3 agrid(BB, HH);                          // (256, 4)
    attn_kernel<<<agrid, 256>>>(probs, u_, a_, out);
}

// round 4
// speedup vs baseline: 3.4262x; 1.2872x over previous
#include <cuda_runtime.h>
#include <math.h>
#include <stdint.h>

// Problem constants
#define BB 256
#define NN 50
#define FF 6144
#define HH 4
#define OO 64
#define NT (HH*OO)          // 256
#define MT (BB*NN)          // 12800

// GEMM tiling
#define BM 128
#define BN 128
#define BK 16
#define PAD 8
#define KSPLIT 2
#define KPER (FF / KSPLIT)  // 3072

// Split-K partial buffers (2 x 13.1 MB); attn sums them on load.
__device__ float g_WhP[(size_t)KSPLIT * MT * NT];

__device__ __forceinline__ unsigned f2tf32(float x) {
    unsigned r;
    asm("cvt.rna.tf32.f32 %0, %1;" : "=r"(r) : "f"(x));
    return r;
}

__device__ __forceinline__ void mma_tf32(float c[4],
                                         const unsigned a[4],
                                         const unsigned b[2]) {
    asm volatile(
        "mma.sync.aligned.m16n8k8.row.col.f32.tf32.tf32.f32 "
        "{%0,%1,%2,%3}, {%4,%5,%6,%7}, {%8,%9}, {%0,%1,%2,%3};"
        : "+f"(c[0]), "+f"(c[1]), "+f"(c[2]), "+f"(c[3])
        : "r"(a[0]), "r"(a[1]), "r"(a[2]), "r"(a[3]),
          "r"(b[0]), "r"(b[1]));
}

// ---------------------------------------------------------------------------
// Kernel A: Wh = h @ W' via tf32 mma.sync, split-K=2.
// grid (100, 2, 2): (M tile, N tile, k split). 256 threads, warp tile 32x64.
// ---------------------------------------------------------------------------
__global__ __launch_bounds__(256, 2)
void gemm_tc(const float* __restrict__ hmat, const float* __restrict__ W)
{
    __shared__ float As[2][BK][BM + PAD];
    __shared__ float Bs[2][BK][BN + PAD];

    const int tid  = threadIdx.x;
    const int lane = tid & 31;
    const int wid  = tid >> 5;
    const int wm   = wid & 3;
    const int wn   = wid >> 2;
    const int row0 = blockIdx.x * BM;
    const int col0 = blockIdx.y * BN;
    const int kz0  = blockIdx.z * KPER;

    float acc[2][8][4];
#pragma unroll
    for (int mt = 0; mt < 2; mt++)
#pragma unroll
        for (int nt = 0; nt < 8; nt++)
#pragma unroll
            for (int i = 0; i < 4; i++) acc[mt][nt][i] = 0.f;

    float4 va[2], vb[2];
    const float* Abase = hmat + (size_t)row0 * FF;

#define LDG_TILE(k0)                                                          \
    {                                                                         \
        _Pragma("unroll")                                                     \
        for (int i = 0; i < 2; i++) {                                         \
            int p = tid + i * 256;                                            \
            int m = p >> 2, kq = (p & 3) * 4;                                 \
            va[i] = *(const float4*)(Abase + (size_t)m * FF + (k0) + kq);     \
        }                                                                     \
        _Pragma("unroll")                                                     \
        for (int i = 0; i < 2; i++) {                                         \
            int p = tid + i * 256;                                            \
            int k = p >> 5, n = (p & 31) * 4;                                 \
            int c = col0 + n;                                                 \
            int hh = c >> 6, oo = c & 63;                                     \
            vb[i] = *(const float4*)(W + (size_t)hh * FF * OO +               \
                                     (size_t)((k0) + k) * OO + oo);           \
        }                                                                     \
    }

#define STS_TILE(buf)                                                         \
    {                                                                         \
        _Pragma("unroll")                                                     \
        for (int i = 0; i < 2; i++) {                                         \
            int p = tid + i * 256;                                            \
            int m = p >> 2, kq = (p & 3) * 4;                                 \
            As[buf][kq + 0][m] = __uint_as_float(f2tf32(va[i].x));            \
            As[buf][kq + 1][m] = __uint_as_float(f2tf32(va[i].y));            \
            As[buf][kq + 2][m] = __uint_as_float(f2tf32(va[i].z));            \
            As[buf][kq + 3][m] = __uint_as_float(f2tf32(va[i].w));            \
        }                                                                     \
        _Pragma("unroll")                                                     \
        for (int i = 0; i < 2; i++) {                                         \
            int p = tid + i * 256;                                            \
            int k = p >> 5, n = (p & 31) * 4;                                 \
            Bs[buf][k][n + 0] = __uint_as_float(f2tf32(vb[i].x));             \
            Bs[buf][k][n + 1] = __uint_as_float(f2tf32(vb[i].y));             \
            Bs[buf][k][n + 2] = __uint_as_float(f2tf32(vb[i].z));             \
            Bs[buf][k][n + 3] = __uint_as_float(f2tf32(vb[i].w));             \
        }                                                                     \
    }

    LDG_TILE(kz0);
    STS_TILE(0);
    __syncthreads();

    const int nKT = KPER / BK;      // 192
    for (int kt = 0; kt < nKT; kt++) {
        const int cur = kt & 1;
        if (kt + 1 < nKT) LDG_TILE(kz0 + (kt + 1) * BK);

#pragma unroll
        for (int ks = 0; ks < 2; ks++) {
            unsigned a[2][4], b[8][2];
            const int kA = ks * 8 + (lane & 3);
            const int mA = wm * 32 + (lane >> 2);
#pragma unroll
            for (int mt = 0; mt < 2; mt++) {
                int m = mA + mt * 16;
                a[mt][0] = __float_as_uint(As[cur][kA    ][m]);
                a[mt][1] = __float_as_uint(As[cur][kA    ][m + 8]);
                a[mt][2] = __float_as_uint(As[cur][kA + 4][m]);
                a[mt][3] = __float_as_uint(As[cur][kA + 4][m + 8]);
            }
            const int nB = wn * 64 + (lane >> 2);
#pragma unroll
            for (int nt = 0; nt < 8; nt++) {
                int n = nB + nt * 8;
                b[nt][0] = __float_as_uint(Bs[cur][kA    ][n]);
                b[nt][1] = __float_as_uint(Bs[cur][kA + 4][n]);
            }
#pragma unroll
            for (int mt = 0; mt < 2; mt++)
#pragma unroll
                for (int nt = 0; nt < 8; nt++)
                    mma_tf32(acc[mt][nt], a[mt], b[nt]);
        }

        if (kt + 1 < nKT) STS_TILE(cur ^ 1);
        __syncthreads();
    }

    float* dst = g_WhP + (size_t)blockIdx.z * MT * NT;
#pragma unroll
    for (int mt = 0; mt < 2; mt++) {
        int r = row0 + wm * 32 + mt * 16 + (lane >> 2);
#pragma unroll
        for (int nt = 0; nt < 8; nt++) {
            int c = col0 + wn * 64 + nt * 8 + (lane & 3) * 2;
            *(float2*)&dst[(size_t)r * NT + c] =
                make_float2(acc[mt][nt][0], acc[mt][nt][1]);
            *(float2*)&dst[(size_t)(r + 8) * NT + c] =
                make_float2(acc[mt][nt][2], acc[mt][nt][3]);
        }
    }
#undef LDG_TILE
#undef STS_TILE
}

// ---------------------------------------------------------------------------
// Kernel B: fused Gumbel adjacency + GAT attention + ELU. grid (256,4).
// Register-tiled 4x4 inner GEMMs (LDS-byte bound previously).
// Rows padded to 52 (zero) so 4x4 tiles need no bounds checks.
// ---------------------------------------------------------------------------
#define NP 52
__global__ __launch_bounds__(256)
void attn_kernel(const float* __restrict__ probs,
                 const float* __restrict__ u,
                 const float* __restrict__ a,
                 float* __restrict__ out)
{
    __shared__ float sWh[NP][68];       // 68 stride: float4-aligned rows
    __shared__ float sA2[NP][68];
    __shared__ float sE[NP][NP];
    __shared__ float sS1[NN];
    __shared__ unsigned char sAdj[NN * NN];

    const int b    = blockIdx.x;
    const int h    = blockIdx.y;
    const int tid  = threadIdx.x;
    const int lane = tid & 31;
    const int wid  = tid >> 5;

    // adjacency
    for (int idx = tid; idx < NN * NN; idx += 256) {
        float p  = probs[(size_t)b * (NN * NN) + idx];
        float u0 = u[((size_t)b * (NN * NN) + idx) * 2 + 0];
        float u1 = u[((size_t)b * (NN * NN) + idx) * 2 + 1];
        float x0 = p, x1 = 1.f - p;
        float mx = fmaxf(x0, x1);
        float e0 = __expf(x0 - mx), e1 = __expf(x1 - mx);
        float inv = 1.f / (e0 + e1);
        float l0 = __logf(e0 * inv + 1e-5f);
        float l1 = __logf(e1 * inv + 1e-5f);
        float g0 = -__logf(-__logf(u0 + 1e-10f) + 1e-10f);
        float g1 = -__logf(-__logf(u1 + 1e-10f) + 1e-10f);
        sAdj[idx] = (l0 + g0 >= l1 + g1) ? 1 : 0;
    }

    // zero pad rows 50..51
    for (int c = tid; c < 2 * 68; c += 256) {
        int r = 50 + (c >> 6 >= 1 ? ((c / 68) ) : 0); // avoid div tricks; do plainly below
    }
    if (tid < 2 * 68) {
        int r = 50 + tid / 68, c = tid % 68;
        sWh[r][c] = 0.f;
        sA2[r][c] = 0.f;
    }

    // load Wh (= sum of split-K partials) and a2
    const float* whA = g_WhP;
    const float* whB = g_WhP + (size_t)MT * NT;
    for (int idx = tid; idx < NN * OO / 4; idx += 256) {
        int n_ = idx >> 4;
        int o4 = (idx & 15) * 4;
        float4 w1 = *(const float4*)&whA[(size_t)(b * NN + n_) * NT + h * OO + o4];
        float4 w2 = *(const float4*)&whB[(size_t)(b * NN + n_) * NT + h * OO + o4];
        float4 av = *(const float4*)&a[(size_t)(h * NN + n_) * (2 * OO) + OO + o4];
        float4 w = make_float4(w1.x + w2.x, w1.y + w2.y, w1.z + w2.z, w1.w + w2.w);
        *(float4*)&sWh[n_][o4] = w;
        *(float4*)&sA2[n_][o4] = av;
    }
    __syncthreads();

    // s1[n] = <Wh[n], a1[n]>
    for (int n_ = wid; n_ < NN; n_ += 8) {
        float a1v0 = a[(size_t)(h * NN + n_) * (2 * OO) + lane];
        float a1v1 = a[(size_t)(h * NN + n_) * (2 * OO) + lane + 32];
        float v = sWh[n_][lane] * a1v0 + sWh[n_][lane + 32] * a1v1;
#pragma unroll
        for (int off = 16; off; off >>= 1) v += __shfl_xor_sync(0xffffffffu, v, off);
        if (lane == 0) sS1[n_] = v;
    }

    // s2[n][m] = <a2[n], Wh[m]> : 13x13 grid of 4x4 register tiles
    if (tid < 169) {
        const int n0 = (tid / 13) * 4;
        const int m0 = (tid % 13) * 4;
        float acc[4][4];
#pragma unroll
        for (int i = 0; i < 4; i++)
#pragma unroll
            for (int j = 0; j < 4; j++) acc[i][j] = 0.f;
#pragma unroll 8
        for (int o = 0; o < OO; o++) {
            float av[4], wv[4];
#pragma unroll
            for (int i = 0; i < 4; i++) av[i] = sA2[n0 + i][o];
#pragma unroll
            for (int j = 0; j < 4; j++) wv[j] = sWh[m0 + j][o];
#pragma unroll
            for (int i = 0; i < 4; i++)
#pragma unroll
                for (int j = 0; j < 4; j++)
                    acc[i][j] = fmaf(av[i], wv[j], acc[i][j]);
        }
#pragma unroll
        for (int i = 0; i < 4; i++)
#pragma unroll
            for (int j = 0; j < 4; j++) sE[n0 + i][m0 + j] = acc[i][j];
    }
    __syncthreads();

    // leaky + mask + row softmax
    for (int n_ = wid; n_ < NN; n_ += 8) {
        float s1v = sS1[n_];
        int m0 = lane, m1 = lane + 32;
        float t0 = s1v + sE[n_][m0];
        t0 = (t0 >= 0.f) ? t0 : 0.2f * t0;
        float v0 = sAdj[n_ * NN + m0] ? t0 : -9e15f;
        float v1 = -9e15f;
        if (m1 < NN) {
            float t1 = s1v + sE[n_][m1];
            t1 = (t1 >= 0.f) ? t1 : 0.2f * t1;
            v1 = sAdj[n_ * NN + m1] ? t1 : -9e15f;
        }
        float mx = fmaxf(v0, v1);
#pragma unroll
        for (int off = 16; off; off >>= 1)
            mx = fmaxf(mx, __shfl_xor_sync(0xffffffffu, mx, off));
        float e0_ = __expf(v0 - mx);
        float e1_ = (m1 < NN) ? __expf(v1 - mx) : 0.f;
        float sum = e0_ + e1_;
#pragma unroll
        for (int off = 16; off; off >>= 1)
            sum += __shfl_xor_sync(0xffffffffu, sum, off);
        float inv = 1.f / sum;
        sE[n_][m0] = e0_ * inv;
        if (m1 < NN) sE[n_][m1] = e1_ * inv;
    }
    __syncthreads();

    // h_prime + ELU: 13(n-tiles) x 16(float4 o) = 208 threads, 4 rows each
    if (tid < 208) {
        const int n0 = (tid / 16) * 4;
        const int o4 = (tid % 16) * 4;
        float4 acc[4];
#pragma unroll
        for (int i = 0; i < 4; i++) acc[i] = make_float4(0.f, 0.f, 0.f, 0.f);
#pragma unroll 5
        for (int m = 0; m < NN; m++) {
            float4 wv = *(const float4*)&sWh[m][o4];
#pragma unroll
            for (int i = 0; i < 4; i++) {
                float at = sE[n0 + i][m];
                acc[i].x = fmaf(at, wv.x, acc[i].x);
                acc[i].y = fmaf(at, wv.y, acc[i].y);
                acc[i].z = fmaf(at, wv.z, acc[i].z);
                acc[i].w = fmaf(at, wv.w, acc[i].w);
            }
        }
#pragma unroll
        for (int i = 0; i < 4; i++) {
            int n_ = n0 + i;
            if (n_ < NN) {
                float4 wv = *(const float4*)&sWh[n_][o4];
                float4 v = make_float4(acc[i].x + 0.3f * wv.x,
                                       acc[i].y + 0.3f * wv.y,
                                       acc[i].z + 0.3f * wv.z,
                                       acc[i].w + 0.3f * wv.w);
                v.x = (v.x > 0.f) ? v.x : expm1f(v.x);
                v.y = (v.y > 0.f) ? v.y : expm1f(v.y);
                v.z = (v.z > 0.f) ? v.z : expm1f(v.z);
                v.w = (v.w > 0.f) ? v.w : expm1f(v.w);
                *(float4*)&out[(size_t)(b * NN + n_) * NT + h * OO + o4] = v;
            }
        }
    }
}

// ---------------------------------------------------------------------------
extern "C" void kernel_launch(void* const* d_in, const int* in_sizes, int n_in,
                              void* d_out, int out_size)
{
    const float* h_    = (const float*)d_in[0];  // (B, N, F)
    const float* probs = (const float*)d_in[1];  // (B, N*N)
    const float* u_    = (const float*)d_in[2];  // (B, N*N, 2)
    const float* W_    = (const float*)d_in[3];  // (H, F, O)
    const float* a_    = (const float*)d_in[4];  // (H, N, 2*O)
    float* out = (float*)d_out;

    dim3 ggrid(MT / BM, NT / BN, KSPLIT);        // (100, 2, 2)
    gemm_tc<<<ggrid, 256>>>(h_, W_);

    dim3 agrid(BB, HH);                          // (256, 4)
    attn_kernel<<<agrid, 256>>>(probs, u_, a_, out);
}

// round 5
// speedup vs baseline: 3.8650x; 1.1281x over previous
#include <cuda_runtime.h>
#include <math.h>
#include <stdint.h>

// Problem constants
#define BB 256
#define NN 50
#define FF 6144
#define HH 4
#define OO 64
#define NT (HH*OO)          // 256
#define MT (BB*NN)          // 12800

// GEMM tiling
#define BM 128
#define BN 128
#define BK 16
#define PAD 8
#define NTILES ((MT/BM) * (NT/BN))     // 200
#define KUNITS (FF/BK)                 // 384 per tile
#define UNITS_TOTAL (NTILES * KUNITS)  // 76800
#define GRID_G 296                     // 2 CTAs per SM, perfectly balanced

__device__ float g_Wh[(size_t)MT * NT];          // 13.1 MB, zeroed per launch
__device__ unsigned char g_adj[(size_t)BB * NN * NN];  // 640 KB

__device__ __forceinline__ unsigned f2tf32(float x) {
    unsigned r;
    asm("cvt.rna.tf32.f32 %0, %1;" : "=r"(r) : "f"(x));
    return r;
}

__device__ __forceinline__ void mma_tf32(float c[4],
                                         const unsigned a[4],
                                         const unsigned b[2]) {
    asm volatile(
        "mma.sync.aligned.m16n8k8.row.col.f32.tf32.tf32.f32 "
        "{%0,%1,%2,%3}, {%4,%5,%6,%7}, {%8,%9}, {%0,%1,%2,%3};"
        : "+f"(c[0]), "+f"(c[1]), "+f"(c[2]), "+f"(c[3])
        : "r"(a[0]), "r"(a[1]), "r"(a[2]), "r"(a[3]),
          "r"(b[0]), "r"(b[1]));
}

// ---------------------------------------------------------------------------
// zero g_Wh
// ---------------------------------------------------------------------------
__global__ void zero_kernel()
{
    size_t i = (size_t)blockIdx.x * blockDim.x + threadIdx.x;
    float4* p = (float4*)g_Wh;
    size_t n4 = (size_t)MT * NT / 4;
    for (; i < n4; i += (size_t)gridDim.x * blockDim.x)
        p[i] = make_float4(0.f, 0.f, 0.f, 0.f);
}

// ---------------------------------------------------------------------------
// adjacency: one pass over B*N*N Gumbel comparisons
// ---------------------------------------------------------------------------
__global__ __launch_bounds__(256)
void adj_kernel(const float* __restrict__ probs, const float* __restrict__ u)
{
    int idx = blockIdx.x * 256 + threadIdx.x;
    if (idx >= BB * NN * NN) return;
    float p = probs[idx];
    float2 uv = *(const float2*)&u[(size_t)idx * 2];
    float x0 = p, x1 = 1.f - p;
    float mx = fmaxf(x0, x1);
    float e0 = __expf(x0 - mx), e1 = __expf(x1 - mx);
    float inv = 1.f / (e0 + e1);
    float l0 = __logf(e0 * inv + 1e-5f);
    float l1 = __logf(e1 * inv + 1e-5f);
    float g0 = -__logf(-__logf(uv.x + 1e-10f) + 1e-10f);
    float g1 = -__logf(-__logf(uv.y + 1e-10f) + 1e-10f);
    g_adj[idx] = (l0 + g0 >= l1 + g1) ? 1 : 0;
}

// ---------------------------------------------------------------------------
// Kernel A: persistent balanced tf32 GEMM. grid=296 CTAs, 256 threads.
// Work = flattened (tile, k-unit) ranges; partial tiles flushed by atomicAdd.
// ---------------------------------------------------------------------------
__global__ __launch_bounds__(256, 2)
void gemm_tc(const float* __restrict__ hmat, const float* __restrict__ W)
{
    __shared__ float As[2][BK][BM + PAD];
    __shared__ float Bs[2][BK][BN + PAD];

    const int tid  = threadIdx.x;
    const int lane = tid & 31;
    const int wid  = tid >> 5;
    const int wm   = wid & 3;
    const int wn   = wid >> 2;

    const int c    = blockIdx.x;
    int u  = (int)(((long long)UNITS_TOTAL * c) / GRID_G);
    const int u1 = (int)(((long long)UNITS_TOTAL * (c + 1)) / GRID_G);

    float4 va[2], vb[2];

#define LDG_TILE(Abase, col0, k0)                                             \
    {                                                                         \
        _Pragma("unroll")                                                     \
        for (int i = 0; i < 2; i++) {                                         \
            int p = tid + i * 256;                                            \
            int m = p >> 2, kq = (p & 3) * 4;                                 \
            va[i] = *(const float4*)((Abase) + (size_t)m * FF + (k0) + kq);   \
        }                                                                     \
        _Pragma("unroll")                                                     \
        for (int i = 0; i < 2; i++) {                                         \
            int p = tid + i * 256;                                            \
            int k = p >> 5, n = (p & 31) * 4;                                 \
            int cc = (col0) + n;                                              \
            int hh = cc >> 6, oo = cc & 63;                                   \
            vb[i] = *(const float4*)(W + (size_t)hh * FF * OO +               \
                                     (size_t)((k0) + k) * OO + oo);           \
        }                                                                     \
    }

#define STS_TILE(buf)                                                         \
    {                                                                         \
        _Pragma("unroll")                                                     \
        for (int i = 0; i < 2; i++) {                                         \
            int p = tid + i * 256;                                            \
            int m = p >> 2, kq = (p & 3) * 4;                                 \
            As[buf][kq + 0][m] = __uint_as_float(f2tf32(va[i].x));            \
            As[buf][kq + 1][m] = __uint_as_float(f2tf32(va[i].y));            \
            As[buf][kq + 2][m] = __uint_as_float(f2tf32(va[i].z));            \
            As[buf][kq + 3][m] = __uint_as_float(f2tf32(va[i].w));            \
        }                                                                     \
        _Pragma("unroll")                                                     \
        for (int i = 0; i < 2; i++) {                                         \
            int p = tid + i * 256;                                            \
            int k = p >> 5, n = (p & 31) * 4;                                 \
            Bs[buf][k][n + 0] = __uint_as_float(f2tf32(vb[i].x));             \
            Bs[buf][k][n + 1] = __uint_as_float(f2tf32(vb[i].y));             \
            Bs[buf][k][n + 2] = __uint_as_float(f2tf32(vb[i].z));             \
            Bs[buf][k][n + 3] = __uint_as_float(f2tf32(vb[i].w));             \
        }                                                                     \
    }

    while (u < u1) {
        const int tile = u / KUNITS;
        const int kbeg = u - tile * KUNITS;
        const int seg  = min(KUNITS - kbeg, u1 - u);
        const int kend = kbeg + seg;
        const int mt   = tile >> 1;
        const int nt   = tile & 1;
        const int row0 = mt * BM;
        const int col0 = nt * BN;
        const float* Abase = hmat + (size_t)row0 * FF;

        float acc[2][8][4];
#pragma unroll
        for (int i = 0; i < 2; i++)
#pragma unroll
            for (int j = 0; j < 8; j++)
#pragma unroll
                for (int q = 0; q < 4; q++) acc[i][j][q] = 0.f;

        LDG_TILE(Abase, col0, kbeg * BK);
        STS_TILE(0);
        __syncthreads();

        for (int kt = kbeg; kt < kend; kt++) {
            const int cur = (kt - kbeg) & 1;
            if (kt + 1 < kend) LDG_TILE(Abase, col0, (kt + 1) * BK);

#pragma unroll
            for (int ks = 0; ks < 2; ks++) {
                unsigned a[2][4], b[8][2];
                const int kA = ks * 8 + (lane & 3);
                const int mA = wm * 32 + (lane >> 2);
#pragma unroll
                for (int mtr = 0; mtr < 2; mtr++) {
                    int m = mA + mtr * 16;
                    a[mtr][0] = __float_as_uint(As[cur][kA    ][m]);
                    a[mtr][1] = __float_as_uint(As[cur][kA    ][m + 8]);
                    a[mtr][2] = __float_as_uint(As[cur][kA + 4][m]);
                    a[mtr][3] = __float_as_uint(As[cur][kA + 4][m + 8]);
                }
                const int nB = wn * 64 + (lane >> 2);
#pragma unroll
                for (int ntr = 0; ntr < 8; ntr++) {
                    int n = nB + ntr * 8;
                    b[ntr][0] = __float_as_uint(Bs[cur][kA    ][n]);
                    b[ntr][1] = __float_as_uint(Bs[cur][kA + 4][n]);
                }
#pragma unroll
                for (int mtr = 0; mtr < 2; mtr++)
#pragma unroll
                    for (int ntr = 0; ntr < 8; ntr++)
                        mma_tf32(acc[mtr][ntr], a[mtr], b[ntr]);
            }

            if (kt + 1 < kend) STS_TILE(cur ^ 1);
            __syncthreads();
        }

        // flush partial tile via atomicAdd
#pragma unroll
        for (int mtr = 0; mtr < 2; mtr++) {
            int r = row0 + wm * 32 + mtr * 16 + (lane >> 2);
#pragma unroll
            for (int ntr = 0; ntr < 8; ntr++) {
                int cc = col0 + wn * 64 + ntr * 8 + (lane & 3) * 2;
                atomicAdd(&g_Wh[(size_t)r * NT + cc],     acc[mtr][ntr][0]);
                atomicAdd(&g_Wh[(size_t)r * NT + cc + 1], acc[mtr][ntr][1]);
                atomicAdd(&g_Wh[(size_t)(r + 8) * NT + cc],     acc[mtr][ntr][2]);
                atomicAdd(&g_Wh[(size_t)(r + 8) * NT + cc + 1], acc[mtr][ntr][3]);
            }
        }

        u += seg;
    }
#undef LDG_TILE
#undef STS_TILE
}

// ---------------------------------------------------------------------------
// Kernel B: GAT attention + ELU. grid (256,4), 256 threads, 5 blocks/SM.
// ---------------------------------------------------------------------------
#define NP 52
__global__ __launch_bounds__(256, 5)
void attn_kernel(const float* __restrict__ a, float* __restrict__ out)
{
    __shared__ float sWh[NP][68];
    __shared__ float sA2[NP][68];
    __shared__ float sE[NP][NP];
    __shared__ float sS1[NN];
    __shared__ unsigned char sAdj[NN * NN];

    const int b    = blockIdx.x;
    const int h    = blockIdx.y;
    const int tid  = threadIdx.x;
    const int lane = tid & 31;
    const int wid  = tid >> 5;

    // load adjacency mask (2500 B = 625 words)
    {
        const unsigned* src = (const unsigned*)(g_adj + (size_t)b * NN * NN);
        unsigned* dst = (unsigned*)sAdj;
        for (int i = tid; i < NN * NN / 4; i += 256) dst[i] = src[i];
    }

    // zero pad rows 50..51
    if (tid < 2 * 68) {
        int r = 50 + tid / 68, cidx = tid % 68;
        sWh[r][cidx] = 0.f;
        sA2[r][cidx] = 0.f;
    }

    // load Wh tile and a2
    for (int idx = tid; idx < NN * OO / 4; idx += 256) {
        int n_ = idx >> 4;
        int o4 = (idx & 15) * 4;
        float4 w  = *(const float4*)&g_Wh[(size_t)(b * NN + n_) * NT + h * OO + o4];
        float4 av = *(const float4*)&a[(size_t)(h * NN + n_) * (2 * OO) + OO + o4];
        *(float4*)&sWh[n_][o4] = w;
        *(float4*)&sA2[n_][o4] = av;
    }
    __syncthreads();

    // s1[n] = <Wh[n], a1[n]>
    for (int n_ = wid; n_ < NN; n_ += 8) {
        float a1v0 = a[(size_t)(h * NN + n_) * (2 * OO) + lane];
        float a1v1 = a[(size_t)(h * NN + n_) * (2 * OO) + lane + 32];
        float v = sWh[n_][lane] * a1v0 + sWh[n_][lane + 32] * a1v1;
#pragma unroll
        for (int off = 16; off; off >>= 1) v += __shfl_xor_sync(0xffffffffu, v, off);
        if (lane == 0) sS1[n_] = v;
    }

    // s2[n][m] = <a2[n], Wh[m]> : 13x13 grid of 4x4 register tiles
    if (tid < 169) {
        const int n0 = (tid / 13) * 4;
        const int m0 = (tid % 13) * 4;
        float acc[4][4];
#pragma unroll
        for (int i = 0; i < 4; i++)
#pragma unroll
            for (int j = 0; j < 4; j++) acc[i][j] = 0.f;
#pragma unroll 8
        for (int o = 0; o < OO; o++) {
            float av[4], wv[4];
#pragma unroll
            for (int i = 0; i < 4; i++) av[i] = sA2[n0 + i][o];
#pragma unroll
            for (int j = 0; j < 4; j++) wv[j] = sWh[m0 + j][o];
#pragma unroll
            for (int i = 0; i < 4; i++)
#pragma unroll
                for (int j = 0; j < 4; j++)
                    acc[i][j] = fmaf(av[i], wv[j], acc[i][j]);
        }
#pragma unroll
        for (int i = 0; i < 4; i++)
#pragma unroll
            for (int j = 0; j < 4; j++) sE[n0 + i][m0 + j] = acc[i][j];
    }
    __syncthreads();

    // leaky + mask + row softmax (warp per row, 2 elems/lane)
    for (int n_ = wid; n_ < NN; n_ += 8) {
        float s1v = sS1[n_];
        int m0 = lane, m1 = lane + 32;
        float t0 = s1v + sE[n_][m0];
        t0 = (t0 >= 0.f) ? t0 : 0.2f * t0;
        float v0 = sAdj[n_ * NN + m0] ? t0 : -9e15f;
        float v1 = -9e15f;
        if (m1 < NN) {
            float t1 = s1v + sE[n_][m1];
            t1 = (t1 >= 0.f) ? t1 : 0.2f * t1;
            v1 = sAdj[n_ * NN + m1] ? t1 : -9e15f;
        }
        float mx = fmaxf(v0, v1);
#pragma unroll
        for (int off = 16; off; off >>= 1)
            mx = fmaxf(mx, __shfl_xor_sync(0xffffffffu, mx, off));
        float e0_ = __expf(v0 - mx);
        float e1_ = (m1 < NN) ? __expf(v1 - mx) : 0.f;
        float sum = e0_ + e1_;
#pragma unroll
        for (int off = 16; off; off >>= 1)
            sum += __shfl_xor_sync(0xffffffffu, sum, off);
        float inv = 1.f / sum;
        sE[n_][m0] = e0_ * inv;
        if (m1 < NN) sE[n_][m1] = e1_ * inv;
    }
    __syncthreads();

    // h_prime + ELU: 13(n-tiles) x 16(float4 o) = 208 threads
    if (tid < 208) {
        const int n0 = (tid / 16) * 4;
        const int o4 = (tid % 16) * 4;
        float4 acc[4];
#pragma unroll
        for (int i = 0; i < 4; i++) acc[i] = make_float4(0.f, 0.f, 0.f, 0.f);
#pragma unroll 5
        for (int m = 0; m < NN; m++) {
            float4 wv = *(const float4*)&sWh[m][o4];
#pragma unroll
            for (int i = 0; i < 4; i++) {
                float at = sE[n0 + i][m];
                acc[i].x = fmaf(at, wv.x, acc[i].x);
                acc[i].y = fmaf(at, wv.y, acc[i].y);
                acc[i].z = fmaf(at, wv.z, acc[i].z);
                acc[i].w = fmaf(at, wv.w, acc[i].w);
            }
        }
#pragma unroll
        for (int i = 0; i < 4; i++) {
            int n_ = n0 + i;
            if (n_ < NN) {
                float4 wv = *(const float4*)&sWh[n_][o4];
                float4 v = make_float4(acc[i].x + 0.3f * wv.x,
                                       acc[i].y + 0.3f * wv.y,
                                       acc[i].z + 0.3f * wv.z,
                                       acc[i].w + 0.3f * wv.w);
                v.x = (v.x > 0.f) ? v.x : expm1f(v.x);
                v.y = (v.y > 0.f) ? v.y : expm1f(v.y);
                v.z = (v.z > 0.f) ? v.z : expm1f(v.z);
                v.w = (v.w > 0.f) ? v.w : expm1f(v.w);
                *(float4*)&out[(size_t)(b * NN + n_) * NT + h * OO + o4] = v;
            }
        }
    }
}

// ---------------------------------------------------------------------------
extern "C" void kernel_launch(void* const* d_in, const int* in_sizes, int n_in,
                              void* d_out, int out_size)
{
    const float* h_    = (const float*)d_in[0];  // (B, N, F)
    const float* probs = (const float*)d_in[1];  // (B, N*N)
    const float* u_    = (const float*)d_in[2];  // (B, N*N, 2)
    const float* W_    = (const float*)d_in[3];  // (H, F, O)
    const float* a_    = (const float*)d_in[4];  // (H, N, 2*O)
    float* out = (float*)d_out;

    zero_kernel<<<592, 256>>>();
    adj_kernel<<<(BB * NN * NN + 255) / 256, 256>>>(probs, u_);
    gemm_tc<<<GRID_G, 256>>>(h_, W_);

    dim3 agrid(BB, HH);
    attn_kernel<<<agrid, 256>>>(a_, out);
}

// round 6
// speedup vs baseline: 5.9502x; 1.5395x over previous
#include <cuda_runtime.h>
#include <cuda_fp16.h>
#include <math.h>
#include <stdint.h>

// Problem constants
#define BB 256
#define NN 50
#define FF 6144
#define HH 4
#define OO 64
#define NT (HH*OO)          // 256
#define MT (BB*NN)          // 12800

// GEMM tiling (fp16 MMA)
#define BM 128
#define BN 128
#define BK 32
#define PADH 8                          // pad in halves -> row stride 40 halves
#define NTILES ((MT/BM) * (NT/BN))      // 200
#define KUNITS (FF/BK)                  // 192
#define UNITS_TOTAL (NTILES * KUNITS)   // 38400
#define GRID_G 296                      // 2 CTAs/SM, balanced

__device__ float  g_Wh[(size_t)MT * NT];              // 13.1 MB, zeroed per launch
__device__ __half g_Bth[(size_t)NT * FF];             // 3.1 MB, fp16 B, K-major
__device__ unsigned char g_adj[(size_t)BB * NN * NN]; // 640 KB

__device__ __forceinline__ void mma_f16(float c[4],
                                        const unsigned a[4],
                                        const unsigned b[2]) {
    asm volatile(
        "mma.sync.aligned.m16n8k16.row.col.f32.f16.f16.f32 "
        "{%0,%1,%2,%3}, {%4,%5,%6,%7}, {%8,%9}, {%0,%1,%2,%3};"
        : "+f"(c[0]), "+f"(c[1]), "+f"(c[2]), "+f"(c[3])
        : "r"(a[0]), "r"(a[1]), "r"(a[2]), "r"(a[3]),
          "r"(b[0]), "r"(b[1]));
}

// ---------------------------------------------------------------------------
__global__ void zero_kernel()
{
    size_t i = (size_t)blockIdx.x * blockDim.x + threadIdx.x;
    float4* p = (float4*)g_Wh;
    size_t n4 = (size_t)MT * NT / 4;
    for (; i < n4; i += (size_t)gridDim.x * blockDim.x)
        p[i] = make_float4(0.f, 0.f, 0.f, 0.f);
}

// ---------------------------------------------------------------------------
// adjacency: one pass over B*N*N Gumbel comparisons
// ---------------------------------------------------------------------------
__global__ __launch_bounds__(256)
void adj_kernel(const float* __restrict__ probs, const float* __restrict__ u)
{
    int idx = blockIdx.x * 256 + threadIdx.x;
    if (idx >= BB * NN * NN) return;
    float p = probs[idx];
    float2 uv = *(const float2*)&u[(size_t)idx * 2];
    float x0 = p, x1 = 1.f - p;
    float mx = fmaxf(x0, x1);
    float e0 = __expf(x0 - mx), e1 = __expf(x1 - mx);
    float inv = 1.f / (e0 + e1);
    float l0 = __logf(e0 * inv + 1e-5f);
    float l1 = __logf(e1 * inv + 1e-5f);
    float g0 = -__logf(-__logf(uv.x + 1e-10f) + 1e-10f);
    float g1 = -__logf(-__logf(uv.y + 1e-10f) + 1e-10f);
    g_adj[idx] = (l0 + g0 >= l1 + g1) ? 1 : 0;
}

// ---------------------------------------------------------------------------
// W (H,F,O) fp32 -> g_Bth[n=h*64+o][k=f] fp16 (transpose + convert)
// ---------------------------------------------------------------------------
__global__ __launch_bounds__(256)
void wT_kernel(const float* __restrict__ W)
{
    __shared__ float t[32][65];
    const int f0 = blockIdx.x * 32;
    const int h  = blockIdx.y;
    for (int i = threadIdx.x; i < 32 * 64; i += 256) {
        int fi = i >> 6, o = i & 63;
        t[fi][o] = W[((size_t)h * FF + f0 + fi) * OO + o];
    }
    __syncthreads();
    for (int i = threadIdx.x; i < 32 * 64; i += 256) {
        int o = i >> 5, fi = i & 31;
        g_Bth[(size_t)(h * 64 + o) * FF + f0 + fi] = __float2half_rn(t[fi][o]);
    }
}

// ---------------------------------------------------------------------------
// Kernel A: persistent balanced fp16 GEMM (fp32 accum). 296 CTAs, 256 thr.
// ---------------------------------------------------------------------------
__global__ __launch_bounds__(256, 2)
void gemm_f16(const float* __restrict__ hmat)
{
    __shared__ __half As[2][BM][BK + PADH];   // [m][k], 10 KB each buf
    __shared__ __half Bs[2][BN][BK + PADH];   // [n][k]

    const int tid  = threadIdx.x;
    const int lane = tid & 31;
    const int wid  = tid >> 5;
    const int wm   = wid & 3;                  // warp row (32 m each)
    const int wn   = wid >> 2;                 // warp col (64 n each)

    const int c  = blockIdx.x;
    int u        = (int)(((long long)UNITS_TOTAL * c) / GRID_G);
    const int u1 = (int)(((long long)UNITS_TOTAL * (c + 1)) / GRID_G);

    float4 va[4];
    int4   vb[2];

    // A tile: 128m x 32k floats = 1024 float4; p -> m = p>>3, kq = (p&7)*4
    // B tile: 128n x 32k halves = 512 int4;    p -> n = p>>2, k8 = (p&3)*8
#define LDG_TILE(Abase, col0, k0)                                             \
    {                                                                         \
        _Pragma("unroll")                                                     \
        for (int i = 0; i < 4; i++) {                                         \
            int p = tid + i * 256;                                            \
            int m = p >> 3, kq = (p & 7) * 4;                                 \
            va[i] = *(const float4*)((Abase) + (size_t)m * FF + (k0) + kq);   \
        }                                                                     \
        _Pragma("unroll")                                                     \
        for (int i = 0; i < 2; i++) {                                         \
            int p = tid + i * 256;                                            \
            int n = p >> 2, k8 = (p & 3) * 8;                                 \
            vb[i] = *(const int4*)&g_Bth[(size_t)((col0) + n) * FF + (k0) + k8]; \
        }                                                                     \
    }

#define STS_TILE(buf)                                                         \
    {                                                                         \
        _Pragma("unroll")                                                     \
        for (int i = 0; i < 4; i++) {                                         \
            int p = tid + i * 256;                                            \
            int m = p >> 3, kq = (p & 7) * 4;                                 \
            *(half2*)&As[buf][m][kq]     = __floats2half2_rn(va[i].x, va[i].y); \
            *(half2*)&As[buf][m][kq + 2] = __floats2half2_rn(va[i].z, va[i].w); \
        }                                                                     \
        _Pragma("unroll")                                                     \
        for (int i = 0; i < 2; i++) {                                         \
            int p = tid + i * 256;                                            \
            int n = p >> 2, k8 = (p & 3) * 8;                                 \
            *(int4*)&Bs[buf][n][k8] = vb[i];                                  \
        }                                                                     \
    }

    while (u < u1) {
        const int tile = u / KUNITS;
        const int kbeg = u - tile * KUNITS;
        const int seg  = min(KUNITS - kbeg, u1 - u);
        const int kend = kbeg + seg;
        const int row0 = (tile >> 1) * BM;
        const int col0 = (tile & 1) * BN;
        const float* Abase = hmat + (size_t)row0 * FF;

        float acc[2][8][4];
#pragma unroll
        for (int i = 0; i < 2; i++)
#pragma unroll
            for (int j = 0; j < 8; j++)
#pragma unroll
                for (int q = 0; q < 4; q++) acc[i][j][q] = 0.f;

        LDG_TILE(Abase, col0, kbeg * BK);
        STS_TILE(0);
        __syncthreads();

        for (int kt = kbeg; kt < kend; kt++) {
            const int cur = (kt - kbeg) & 1;
            if (kt + 1 < kend) LDG_TILE(Abase, col0, (kt + 1) * BK);

#pragma unroll
            for (int ks = 0; ks < 2; ks++) {
                const int kb = ks * 16 + (lane & 3) * 2;
                unsigned a[2][4], b[8][2];
                const int mA = wm * 32 + (lane >> 2);
#pragma unroll
                for (int mt = 0; mt < 2; mt++) {
                    int m = mA + mt * 16;
                    a[mt][0] = *(const unsigned*)&As[cur][m    ][kb];
                    a[mt][1] = *(const unsigned*)&As[cur][m + 8][kb];
                    a[mt][2] = *(const unsigned*)&As[cur][m    ][kb + 8];
                    a[mt][3] = *(const unsigned*)&As[cur][m + 8][kb + 8];
                }
                const int nB = wn * 64 + (lane >> 2);
#pragma unroll
                for (int nt = 0; nt < 8; nt++) {
                    int n = nB + nt * 8;
                    b[nt][0] = *(const unsigned*)&Bs[cur][n][kb];
                    b[nt][1] = *(const unsigned*)&Bs[cur][n][kb + 8];
                }
#pragma unroll
                for (int mt = 0; mt < 2; mt++)
#pragma unroll
                    for (int nt = 0; nt < 8; nt++)
                        mma_f16(acc[mt][nt], a[mt], b[nt]);
            }

            if (kt + 1 < kend) STS_TILE(cur ^ 1);
            __syncthreads();
        }

        // flush tile segment via atomicAdd
#pragma unroll
        for (int mt = 0; mt < 2; mt++) {
            int r = row0 + wm * 32 + mt * 16 + (lane >> 2);
#pragma unroll
            for (int nt = 0; nt < 8; nt++) {
                int cc = col0 + wn * 64 + nt * 8 + (lane & 3) * 2;
                atomicAdd(&g_Wh[(size_t)r * NT + cc],           acc[mt][nt][0]);
                atomicAdd(&g_Wh[(size_t)r * NT + cc + 1],       acc[mt][nt][1]);
                atomicAdd(&g_Wh[(size_t)(r + 8) * NT + cc],     acc[mt][nt][2]);
                atomicAdd(&g_Wh[(size_t)(r + 8) * NT + cc + 1], acc[mt][nt][3]);
            }
        }

        u += seg;
    }
#undef LDG_TILE
#undef STS_TILE
}

// ---------------------------------------------------------------------------
// Kernel B: GAT attention + ELU. grid (256,4), 256 threads, 5 blocks/SM.
// ---------------------------------------------------------------------------
#define NP 52
__global__ __launch_bounds__(256, 5)
void attn_kernel(const float* __restrict__ a, float* __restrict__ out)
{
    __shared__ float sWh[NP][68];
    __shared__ float sA2[NP][68];
    __shared__ float sE[NP][NP];
    __shared__ float sS1[NN];
    __shared__ unsigned char sAdj[NN * NN];

    const int b    = blockIdx.x;
    const int h    = blockIdx.y;
    const int tid  = threadIdx.x;
    const int lane = tid & 31;
    const int wid  = tid >> 5;

    {
        const unsigned* src = (const unsigned*)(g_adj + (size_t)b * NN * NN);
        unsigned* dst = (unsigned*)sAdj;
        for (int i = tid; i < NN * NN / 4; i += 256) dst[i] = src[i];
    }

    if (tid < 2 * 68) {
        int r = 50 + tid / 68, cidx = tid % 68;
        sWh[r][cidx] = 0.f;
        sA2[r][cidx] = 0.f;
    }

    for (int idx = tid; idx < NN * OO / 4; idx += 256) {
        int n_ = idx >> 4;
        int o4 = (idx & 15) * 4;
        float4 w  = *(const float4*)&g_Wh[(size_t)(b * NN + n_) * NT + h * OO + o4];
        float4 av = *(const float4*)&a[(size_t)(h * NN + n_) * (2 * OO) + OO + o4];
        *(float4*)&sWh[n_][o4] = w;
        *(float4*)&sA2[n_][o4] = av;
    }
    __syncthreads();

    for (int n_ = wid; n_ < NN; n_ += 8) {
        float a1v0 = a[(size_t)(h * NN + n_) * (2 * OO) + lane];
        float a1v1 = a[(size_t)(h * NN + n_) * (2 * OO) + lane + 32];
        float v = sWh[n_][lane] * a1v0 + sWh[n_][lane + 32] * a1v1;
#pragma unroll
        for (int off = 16; off; off >>= 1) v += __shfl_xor_sync(0xffffffffu, v, off);
        if (lane == 0) sS1[n_] = v;
    }

    if (tid < 169) {
        const int n0 = (tid / 13) * 4;
        const int m0 = (tid % 13) * 4;
        float acc[4][4];
#pragma unroll
        for (int i = 0; i < 4; i++)
#pragma unroll
            for (int j = 0; j < 4; j++) acc[i][j] = 0.f;
#pragma unroll 8
        for (int o = 0; o < OO; o++) {
            float av[4], wv[4];
#pragma unroll
            for (int i = 0; i < 4; i++) av[i] = sA2[n0 + i][o];
#pragma unroll
            for (int j = 0; j < 4; j++) wv[j] = sWh[m0 + j][o];
#pragma unroll
            for (int i = 0; i < 4; i++)
#pragma unroll
                for (int j = 0; j < 4; j++)
                    acc[i][j] = fmaf(av[i], wv[j], acc[i][j]);
        }
#pragma unroll
        for (int i = 0; i < 4; i++)
#pragma unroll
            for (int j = 0; j < 4; j++) sE[n0 + i][m0 + j] = acc[i][j];
    }
    __syncthreads();

    for (int n_ = wid; n_ < NN; n_ += 8) {
        float s1v = sS1[n_];
        int m0 = lane, m1 = lane + 32;
        float t0 = s1v + sE[n_][m0];
        t0 = (t0 >= 0.f) ? t0 : 0.2f * t0;
        float v0 = sAdj[n_ * NN + m0] ? t0 : -9e15f;
        float v1 = -9e15f;
        if (m1 < NN) {
            float t1 = s1v + sE[n_][m1];
            t1 = (t1 >= 0.f) ? t1 : 0.2f * t1;
            v1 = sAdj[n_ * NN + m1] ? t1 : -9e15f;
        }
        float mx = fmaxf(v0, v1);
#pragma unroll
        for (int off = 16; off; off >>= 1)
            mx = fmaxf(mx, __shfl_xor_sync(0xffffffffu, mx, off));
        float e0_ = __expf(v0 - mx);
        float e1_ = (m1 < NN) ? __expf(v1 - mx) : 0.f;
        float sum = e0_ + e1_;
#pragma unroll
        for (int off = 16; off; off >>= 1)
            sum += __shfl_xor_sync(0xffffffffu, sum, off);
        float inv = 1.f / sum;
        sE[n_][m0] = e0_ * inv;
        if (m1 < NN) sE[n_][m1] = e1_ * inv;
    }
    __syncthreads();

    if (tid < 208) {
        const int n0 = (tid / 16) * 4;
        const int o4 = (tid % 16) * 4;
        float4 acc[4];
#pragma unroll
        for (int i = 0; i < 4; i++) acc[i] = make_float4(0.f, 0.f, 0.f, 0.f);
#pragma unroll 5
        for (int m = 0; m < NN; m++) {
            float4 wv = *(const float4*)&sWh[m][o4];
#pragma unroll
            for (int i = 0; i < 4; i++) {
                float at = sE[n0 + i][m];
                acc[i].x = fmaf(at, wv.x, acc[i].x);
                acc[i].y = fmaf(at, wv.y, acc[i].y);
                acc[i].z = fmaf(at, wv.z, acc[i].z);
                acc[i].w = fmaf(at, wv.w, acc[i].w);
            }
        }
#pragma unroll
        for (int i = 0; i < 4; i++) {
            int n_ = n0 + i;
            if (n_ < NN) {
                float4 wv = *(const float4*)&sWh[n_][o4];
                float4 v = make_float4(acc[i].x + 0.3f * wv.x,
                                       acc[i].y + 0.3f * wv.y,
                                       acc[i].z + 0.3f * wv.z,
                                       acc[i].w + 0.3f * wv.w);
                v.x = (v.x > 0.f) ? v.x : expm1f(v.x);
                v.y = (v.y > 0.f) ? v.y : expm1f(v.y);
                v.z = (v.z > 0.f) ? v.z : expm1f(v.z);
                v.w = (v.w > 0.f) ? v.w : expm1f(v.w);
                *(float4*)&out[(size_t)(b * NN + n_) * NT + h * OO + o4] = v;
            }
        }
    }
}

// ---------------------------------------------------------------------------
extern "C" void kernel_launch(void* const* d_in, const int* in_sizes, int n_in,
                              void* d_out, int out_size)
{
    const float* h_    = (const float*)d_in[0];  // (B, N, F)
    const float* probs = (const float*)d_in[1];  // (B, N*N)
    const float* u_    = (const float*)d_in[2];  // (B, N*N, 2)
    const float* W_    = (const float*)d_in[3];  // (H, F, O)
    const float* a_    = (const float*)d_in[4];  // (H, N, 2*O)
    float* out = (float*)d_out;

    zero_kernel<<<592, 256>>>();
    adj_kernel<<<(BB * NN * NN + 255) / 256, 256>>>(probs, u_);

    dim3 tgrid(FF / 32, HH);
    wT_kernel<<<tgrid, 256>>>(W_);

    gemm_f16<<<GRID_G, 256>>>(h_);

    dim3 agrid(BB, HH);
    attn_kernel<<<agrid, 256>>>(a_, out);
}

// round 7
// speedup vs baseline: 6.3664x; 1.0700x over previous
#include <cuda_runtime.h>
#include <cuda_fp16.h>
#include <math.h>
#include <stdint.h>

// Problem constants
#define BB 256
#define NN 50
#define FF 6144
#define HH 4
#define OO 64
#define NT (HH*OO)          // 256
#define MT (BB*NN)          // 12800

// GEMM tiling (fp16 MMA): CTA tile 128 x 256, full output width
#define BM 128
#define BN 256
#define BK 32
#define RS (BK + 8)                     // smem row stride in halves (40)
#define NTILES (MT/BM)                  // 100
#define KUNITS (FF/BK)                  // 192
#define UNITS_TOTAL (NTILES * KUNITS)   // 19200
#define GRID_G 148                      // 1 CTA/SM, balanced persistent
#define NTHREADS 512

#define SMEM_A_HALVES (2 * BM * RS)     // 10240
#define SMEM_B_HALVES (2 * BN * RS)     // 20480
#define SMEM_BYTES ((SMEM_A_HALVES + SMEM_B_HALVES) * 2)   // 61440

__device__ float  g_Wh[(size_t)MT * NT];              // 13.1 MB, zeroed per launch
__device__ __half g_Bth[(size_t)NT * FF];             // 3.1 MB, fp16 B, K-major
__device__ unsigned char g_adj[(size_t)BB * NN * NN]; // 640 KB

__device__ __forceinline__ void mma_f16(float c[4],
                                        const unsigned a[4],
                                        const unsigned b[2]) {
    asm volatile(
        "mma.sync.aligned.m16n8k16.row.col.f32.f16.f16.f32 "
        "{%0,%1,%2,%3}, {%4,%5,%6,%7}, {%8,%9}, {%0,%1,%2,%3};"
        : "+f"(c[0]), "+f"(c[1]), "+f"(c[2]), "+f"(c[3])
        : "r"(a[0]), "r"(a[1]), "r"(a[2]), "r"(a[3]),
          "r"(b[0]), "r"(b[1]));
}

// ---------------------------------------------------------------------------
__global__ void zero_kernel()
{
    size_t i = (size_t)blockIdx.x * blockDim.x + threadIdx.x;
    float4* p = (float4*)g_Wh;
    size_t n4 = (size_t)MT * NT / 4;
    for (; i < n4; i += (size_t)gridDim.x * blockDim.x)
        p[i] = make_float4(0.f, 0.f, 0.f, 0.f);
}

// ---------------------------------------------------------------------------
__global__ __launch_bounds__(256)
void adj_kernel(const float* __restrict__ probs, const float* __restrict__ u)
{
    int idx = blockIdx.x * 256 + threadIdx.x;
    if (idx >= BB * NN * NN) return;
    float p = probs[idx];
    float2 uv = *(const float2*)&u[(size_t)idx * 2];
    float x0 = p, x1 = 1.f - p;
    float mx = fmaxf(x0, x1);
    float e0 = __expf(x0 - mx), e1 = __expf(x1 - mx);
    float inv = 1.f / (e0 + e1);
    float l0 = __logf(e0 * inv + 1e-5f);
    float l1 = __logf(e1 * inv + 1e-5f);
    float g0 = -__logf(-__logf(uv.x + 1e-10f) + 1e-10f);
    float g1 = -__logf(-__logf(uv.y + 1e-10f) + 1e-10f);
    g_adj[idx] = (l0 + g0 >= l1 + g1) ? 1 : 0;
}

// ---------------------------------------------------------------------------
// W (H,F,O) fp32 -> g_Bth[n=h*64+o][k=f] fp16 (transpose + convert)
// ---------------------------------------------------------------------------
__global__ __launch_bounds__(256)
void wT_kernel(const float* __restrict__ W)
{
    __shared__ float t[32][65];
    const int f0 = blockIdx.x * 32;
    const int h  = blockIdx.y;
    for (int i = threadIdx.x; i < 32 * 64; i += 256) {
        int fi = i >> 6, o = i & 63;
        t[fi][o] = W[((size_t)h * FF + f0 + fi) * OO + o];
    }
    __syncthreads();
    for (int i = threadIdx.x; i < 32 * 64; i += 256) {
        int o = i >> 5, fi = i & 31;
        g_Bth[(size_t)(h * 64 + o) * FF + f0 + fi] = __float2half_rn(t[fi][o]);
    }
}

// ---------------------------------------------------------------------------
// Kernel A: persistent balanced fp16 GEMM, 128x256 CTA tile, 512 threads.
// h streamed from DRAM exactly once.
// ---------------------------------------------------------------------------
__global__ __launch_bounds__(NTHREADS, 1)
void gemm_f16(const float* __restrict__ hmat)
{
    extern __shared__ __half sm[];
    __half* Asm = sm;                     // [2][BM][RS]
    __half* Bsm = sm + SMEM_A_HALVES;     // [2][BN][RS]

    const int tid  = threadIdx.x;
    const int lane = tid & 31;
    const int wid  = tid >> 5;
    const int wm   = wid & 3;             // warp row group: 4 x 32 = 128 m
    const int wn   = wid >> 2;            // warp col group: 4 x 64 = 256 n

    const int c  = blockIdx.x;
    int u        = (int)(((long long)UNITS_TOTAL * c) / GRID_G);
    const int u1 = (int)(((long long)UNITS_TOTAL * (c + 1)) / GRID_G);

    float4 va[2];
    int4   vb[2];

    // A tile: 128m x 32k floats = 1024 float4; p -> m = p>>3, kq = (p&7)*4
    // B tile: 256n x 32k halves = 1024 int4;   p -> n = p>>2, k8 = (p&3)*8
#define LDG_TILE(Abase, k0)                                                   \
    {                                                                         \
        _Pragma("unroll")                                                     \
        for (int i = 0; i < 2; i++) {                                         \
            int p = tid + i * NTHREADS;                                       \
            int m = p >> 3, kq = (p & 7) * 4;                                 \
            va[i] = *(const float4*)((Abase) + (size_t)m * FF + (k0) + kq);   \
        }                                                                     \
        _Pragma("unroll")                                                     \
        for (int i = 0; i < 2; i++) {                                         \
            int p = tid + i * NTHREADS;                                       \
            int n = p >> 2, k8 = (p & 3) * 8;                                 \
            vb[i] = *(const int4*)&g_Bth[(size_t)n * FF + (k0) + k8];         \
        }                                                                     \
    }

#define STS_TILE(buf)                                                         \
    {                                                                         \
        _Pragma("unroll")                                                     \
        for (int i = 0; i < 2; i++) {                                         \
            int p = tid + i * NTHREADS;                                       \
            int m = p >> 3, kq = (p & 7) * 4;                                 \
            __half* dst = Asm + (buf) * BM * RS + m * RS + kq;                \
            *(half2*)(dst)     = __floats2half2_rn(va[i].x, va[i].y);         \
            *(half2*)(dst + 2) = __floats2half2_rn(va[i].z, va[i].w);         \
        }                                                                     \
        _Pragma("unroll")                                                     \
        for (int i = 0; i < 2; i++) {                                         \
            int p = tid + i * NTHREADS;                                       \
            int n = p >> 2, k8 = (p & 3) * 8;                                 \
            *(int4*)(Bsm + (buf) * BN * RS + n * RS + k8) = vb[i];            \
        }                                                                     \
    }

    while (u < u1) {
        const int tile = u / KUNITS;
        const int kbeg = u - tile * KUNITS;
        const int seg  = min(KUNITS - kbeg, u1 - u);
        const int kend = kbeg + seg;
        const int row0 = tile * BM;
        const float* Abase = hmat + (size_t)row0 * FF;

        float acc[2][8][4];
#pragma unroll
        for (int i = 0; i < 2; i++)
#pragma unroll
            for (int j = 0; j < 8; j++)
#pragma unroll
                for (int q = 0; q < 4; q++) acc[i][j][q] = 0.f;

        LDG_TILE(Abase, kbeg * BK);
        STS_TILE(0);
        __syncthreads();

        for (int kt = kbeg; kt < kend; kt++) {
            const int cur = (kt - kbeg) & 1;
            if (kt + 1 < kend) LDG_TILE(Abase, (kt + 1) * BK);

#pragma unroll
            for (int ks = 0; ks < 2; ks++) {
                const int kb = ks * 16 + (lane & 3) * 2;
                unsigned a[2][4], b[8][2];
                const int mA = wm * 32 + (lane >> 2);
                const __half* Ab = Asm + cur * BM * RS;
                const __half* Bb = Bsm + cur * BN * RS;
#pragma unroll
                for (int mt = 0; mt < 2; mt++) {
                    int m = mA + mt * 16;
                    a[mt][0] = *(const unsigned*)(Ab + (m    ) * RS + kb);
                    a[mt][1] = *(const unsigned*)(Ab + (m + 8) * RS + kb);
                    a[mt][2] = *(const unsigned*)(Ab + (m    ) * RS + kb + 8);
                    a[mt][3] = *(const unsigned*)(Ab + (m + 8) * RS + kb + 8);
                }
                const int nB = wn * 64 + (lane >> 2);
#pragma unroll
                for (int nt = 0; nt < 8; nt++) {
                    int n = nB + nt * 8;
                    b[nt][0] = *(const unsigned*)(Bb + n * RS + kb);
                    b[nt][1] = *(const unsigned*)(Bb + n * RS + kb + 8);
                }
#pragma unroll
                for (int mt = 0; mt < 2; mt++)
#pragma unroll
                    for (int nt = 0; nt < 8; nt++)
                        mma_f16(acc[mt][nt], a[mt], b[nt]);
            }

            if (kt + 1 < kend) STS_TILE(cur ^ 1);
            __syncthreads();
        }

        // flush tile segment via atomicAdd
#pragma unroll
        for (int mt = 0; mt < 2; mt++) {
            int r = row0 + wm * 32 + mt * 16 + (lane >> 2);
#pragma unroll
            for (int nt = 0; nt < 8; nt++) {
                int cc = wn * 64 + nt * 8 + (lane & 3) * 2;
                atomicAdd(&g_Wh[(size_t)r * NT + cc],           acc[mt][nt][0]);
                atomicAdd(&g_Wh[(size_t)r * NT + cc + 1],       acc[mt][nt][1]);
                atomicAdd(&g_Wh[(size_t)(r + 8) * NT + cc],     acc[mt][nt][2]);
                atomicAdd(&g_Wh[(size_t)(r + 8) * NT + cc + 1], acc[mt][nt][3]);
            }
        }

        u += seg;
        __syncthreads();
    }
#undef LDG_TILE
#undef STS_TILE
}

// ---------------------------------------------------------------------------
// Kernel B: GAT attention + ELU. grid (256,4), 256 threads, 5 blocks/SM.
// ---------------------------------------------------------------------------
#define NP 52
__global__ __launch_bounds__(256, 5)
void attn_kernel(const float* __restrict__ a, float* __restrict__ out)
{
    __shared__ float sWh[NP][68];
    __shared__ float sA2[NP][68];
    __shared__ float sE[NP][NP];
    __shared__ float sS1[NN];
    __shared__ unsigned char sAdj[NN * NN];

    const int b    = blockIdx.x;
    const int h    = blockIdx.y;
    const int tid  = threadIdx.x;
    const int lane = tid & 31;
    const int wid  = tid >> 5;

    {
        const unsigned* src = (const unsigned*)(g_adj + (size_t)b * NN * NN);
        unsigned* dst = (unsigned*)sAdj;
        for (int i = tid; i < NN * NN / 4; i += 256) dst[i] = src[i];
    }

    if (tid < 2 * 68) {
        int r = 50 + tid / 68, cidx = tid % 68;
        sWh[r][cidx] = 0.f;
        sA2[r][cidx] = 0.f;
    }

    for (int idx = tid; idx < NN * OO / 4; idx += 256) {
        int n_ = idx >> 4;
        int o4 = (idx & 15) * 4;
        float4 w  = *(const float4*)&g_Wh[(size_t)(b * NN + n_) * NT + h * OO + o4];
        float4 av = *(const float4*)&a[(size_t)(h * NN + n_) * (2 * OO) + OO + o4];
        *(float4*)&sWh[n_][o4] = w;
        *(float4*)&sA2[n_][o4] = av;
    }
    __syncthreads();

    for (int n_ = wid; n_ < NN; n_ += 8) {
        float a1v0 = a[(size_t)(h * NN + n_) * (2 * OO) + lane];
        float a1v1 = a[(size_t)(h * NN + n_) * (2 * OO) + lane + 32];
        float v = sWh[n_][lane] * a1v0 + sWh[n_][lane + 32] * a1v1;
#pragma unroll
        for (int off = 16; off; off >>= 1) v += __shfl_xor_sync(0xffffffffu, v, off);
        if (lane == 0) sS1[n_] = v;
    }

    if (tid < 169) {
        const int n0 = (tid / 13) * 4;
        const int m0 = (tid % 13) * 4;
        float acc[4][4];
#pragma unroll
        for (int i = 0; i < 4; i++)
#pragma unroll
            for (int j = 0; j < 4; j++) acc[i][j] = 0.f;
#pragma unroll 8
        for (int o = 0; o < OO; o++) {
            float av[4], wv[4];
#pragma unroll
            for (int i = 0; i < 4; i++) av[i] = sA2[n0 + i][o];
#pragma unroll
            for (int j = 0; j < 4; j++) wv[j] = sWh[m0 + j][o];
#pragma unroll
            for (int i = 0; i < 4; i++)
#pragma unroll
                for (int j = 0; j < 4; j++)
                    acc[i][j] = fmaf(av[i], wv[j], acc[i][j]);
        }
#pragma unroll
        for (int i = 0; i < 4; i++)
#pragma unroll
            for (int j = 0; j < 4; j++) sE[n0 + i][m0 + j] = acc[i][j];
    }
    __syncthreads();

    for (int n_ = wid; n_ < NN; n_ += 8) {
        float s1v = sS1[n_];
        int m0 = lane, m1 = lane + 32;
        float t0 = s1v + sE[n_][m0];
        t0 = (t0 >= 0.f) ? t0 : 0.2f * t0;
        float v0 = sAdj[n_ * NN + m0] ? t0 : -9e15f;
        float v1 = -9e15f;
        if (m1 < NN) {
            float t1 = s1v + sE[n_][m1];
            t1 = (t1 >= 0.f) ? t1 : 0.2f * t1;
            v1 = sAdj[n_ * NN + m1] ? t1 : -9e15f;
        }
        float mx = fmaxf(v0, v1);
#pragma unroll
        for (int off = 16; off; off >>= 1)
            mx = fmaxf(mx, __shfl_xor_sync(0xffffffffu, mx, off));
        float e0_ = __expf(v0 - mx);
        float e1_ = (m1 < NN) ? __expf(v1 - mx) : 0.f;
        float sum = e0_ + e1_;
#pragma unroll
        for (int off = 16; off; off >>= 1)
            sum += __shfl_xor_sync(0xffffffffu, sum, off);
        float inv = 1.f / sum;
        sE[n_][m0] = e0_ * inv;
        if (m1 < NN) sE[n_][m1] = e1_ * inv;
    }
    __syncthreads();

    if (tid < 208) {
        const int n0 = (tid / 16) * 4;
        const int o4 = (tid % 16) * 4;
        float4 acc[4];
#pragma unroll
        for (int i = 0; i < 4; i++) acc[i] = make_float4(0.f, 0.f, 0.f, 0.f);
#pragma unroll 5
        for (int m = 0; m < NN; m++) {
            float4 wv = *(const float4*)&sWh[m][o4];
#pragma unroll
            for (int i = 0; i < 4; i++) {
                float at = sE[n0 + i][m];
                acc[i].x = fmaf(at, wv.x, acc[i].x);
                acc[i].y = fmaf(at, wv.y, acc[i].y);
                acc[i].z = fmaf(at, wv.z, acc[i].z);
                acc[i].w = fmaf(at, wv.w, acc[i].w);
            }
        }
#pragma unroll
        for (int i = 0; i < 4; i++) {
            int n_ = n0 + i;
            if (n_ < NN) {
                float4 wv = *(const float4*)&sWh[n_][o4];
                float4 v = make_float4(acc[i].x + 0.3f * wv.x,
                                       acc[i].y + 0.3f * wv.y,
                                       acc[i].z + 0.3f * wv.z,
                                       acc[i].w + 0.3f * wv.w);
                v.x = (v.x > 0.f) ? v.x : expm1f(v.x);
                v.y = (v.y > 0.f) ? v.y : expm1f(v.y);
                v.z = (v.z > 0.f) ? v.z : expm1f(v.z);
                v.w = (v.w > 0.f) ? v.w : expm1f(v.w);
                *(float4*)&out[(size_t)(b * NN + n_) * NT + h * OO + o4] = v;
            }
        }
    }
}

// ---------------------------------------------------------------------------
extern "C" void kernel_launch(void* const* d_in, const int* in_sizes, int n_in,
                              void* d_out, int out_size)
{
    const float* h_    = (const float*)d_in[0];  // (B, N, F)
    const float* probs = (const float*)d_in[1];  // (B, N*N)
    const float* u_    = (const float*)d_in[2];  // (B, N*N, 2)
    const float* W_    = (const float*)d_in[3];  // (H, F, O)
    const float* a_    = (const float*)d_in[4];  // (H, N, 2*O)
    float* out = (float*)d_out;

    zero_kernel<<<592, 256>>>();
    adj_kernel<<<(BB * NN * NN + 255) / 256, 256>>>(probs, u_);

    dim3 tgrid(FF / 32, HH);
    wT_kernel<<<tgrid, 256>>>(W_);

    cudaFuncSetAttribute(gemm_f16, cudaFuncAttributeMaxDynamicSharedMemorySize,
                         SMEM_BYTES);
    gemm_f16<<<GRID_G, NTHREADS, SMEM_BYTES>>>(h_);

    dim3 agrid(BB, HH);
    attn_kernel<<<agrid, 256>>>(a_, out);
}

// round 8
// speedup vs baseline: 6.6169x; 1.0393x over previous
#include <cuda_runtime.h>
#include <cuda_fp16.h>
#include <math.h>
#include <stdint.h>

// Problem constants
#define BB 256
#define NN 50
#define FF 6144
#define HH 4
#define OO 64
#define NT (HH*OO)          // 256
#define MT (BB*NN)          // 12800

// GEMM tiling: CTA tile 128 x 256 (full width), fp16 MMA, fp32 A in smem
#define BM 128
#define BN 256
#define BK 32
#define RSA 40                          // A row stride (floats): 160 B, 16B-mult
#define RSB 56                          // B row stride (halves): 112 B, 16B-mult
#define NSTG 4
#define A_ST_BYTES (BM * RSA * 4)       // 20480
#define B_ST_BYTES (BN * RSB * 2)       // 28672
#define SMEM_BYTES (NSTG * (A_ST_BYTES + B_ST_BYTES))   // 196608 (192 KB)
#define NTILES (MT/BM)                  // 100
#define KUNITS (FF/BK)                  // 192
#define UNITS_TOTAL (NTILES * KUNITS)   // 19200
#define GRID_G 148
#define NTHREADS 512

__device__ float  g_Wh[(size_t)MT * NT];              // 13.1 MB, zeroed per launch
__device__ __half g_Bth[(size_t)NT * FF];             // 3.1 MB fp16 B, K-major
__device__ unsigned char g_adj[(size_t)BB * NN * NN]; // 640 KB

__device__ __forceinline__ uint32_t smem_u32(const void* p) {
    uint32_t a;
    asm("{ .reg .u64 t; cvta.to.shared.u64 t, %1; cvt.u32.u64 %0, t; }" : "=r"(a) : "l"(p));
    return a;
}
__device__ __forceinline__ unsigned packh2(float x, float y) {
    half2 h = __floats2half2_rn(x, y);
    return *(unsigned*)&h;
}
__device__ __forceinline__ void mma_f16(float c[4],
                                        const unsigned a[4],
                                        const unsigned b[2]) {
    asm volatile(
        "mma.sync.aligned.m16n8k16.row.col.f32.f16.f16.f32 "
        "{%0,%1,%2,%3}, {%4,%5,%6,%7}, {%8,%9}, {%0,%1,%2,%3};"
        : "+f"(c[0]), "+f"(c[1]), "+f"(c[2]), "+f"(c[3])
        : "r"(a[0]), "r"(a[1]), "r"(a[2]), "r"(a[3]),
          "r"(b[0]), "r"(b[1]));
}
#define CP16(dst, src) \
    asm volatile("cp.async.cg.shared.global [%0], [%1], 16;" :: "r"(dst), "l"(src))
#define CP_COMMIT() asm volatile("cp.async.commit_group;" ::: "memory")
#define CP_WAIT2()  asm volatile("cp.async.wait_group 2;"  ::: "memory")

// ---------------------------------------------------------------------------
__global__ void zero_kernel()
{
    size_t i = (size_t)blockIdx.x * blockDim.x + threadIdx.x;
    float4* p = (float4*)g_Wh;
    size_t n4 = (size_t)MT * NT / 4;
    for (; i < n4; i += (size_t)gridDim.x * blockDim.x)
        p[i] = make_float4(0.f, 0.f, 0.f, 0.f);
}

// ---------------------------------------------------------------------------
__global__ __launch_bounds__(256)
void adj_kernel(const float* __restrict__ probs, const float* __restrict__ u)
{
    int idx = blockIdx.x * 256 + threadIdx.x;
    if (idx >= BB * NN * NN) return;
    float p = probs[idx];
    float2 uv = *(const float2*)&u[(size_t)idx * 2];
    float x0 = p, x1 = 1.f - p;
    float mx = fmaxf(x0, x1);
    float e0 = __expf(x0 - mx), e1 = __expf(x1 - mx);
    float inv = 1.f / (e0 + e1);
    float l0 = __logf(e0 * inv + 1e-5f);
    float l1 = __logf(e1 * inv + 1e-5f);
    float g0 = -__logf(-__logf(uv.x + 1e-10f) + 1e-10f);
    float g1 = -__logf(-__logf(uv.y + 1e-10f) + 1e-10f);
    g_adj[idx] = (l0 + g0 >= l1 + g1) ? 1 : 0;
}

// ---------------------------------------------------------------------------
// W (H,F,O) fp32 -> g_Bth[n=h*64+o][k=f] fp16 (transpose + convert)
// ---------------------------------------------------------------------------
__global__ __launch_bounds__(256)
void wT_kernel(const float* __restrict__ W)
{
    __shared__ float t[32][65];
    const int f0 = blockIdx.x * 32;
    const int h  = blockIdx.y;
    for (int i = threadIdx.x; i < 32 * 64; i += 256) {
        int fi = i >> 6, o = i & 63;
        t[fi][o] = W[((size_t)h * FF + f0 + fi) * OO + o];
    }
    __syncthreads();
    for (int i = threadIdx.x; i < 32 * 64; i += 256) {
        int o = i >> 5, fi = i & 31;
        g_Bth[(size_t)(h * 64 + o) * FF + f0 + fi] = __float2half_rn(t[fi][o]);
    }
}

// ---------------------------------------------------------------------------
// Kernel A: persistent fp16 GEMM, cp.async 4-stage, ldmatrix B fragments.
// ---------------------------------------------------------------------------
__global__ __launch_bounds__(NTHREADS, 1)
void gemm_f16(const float* __restrict__ hmat)
{
    extern __shared__ char smraw[];
    float*  Asm = (float*)smraw;
    __half* Bsm = (__half*)(smraw + NSTG * A_ST_BYTES);
    const uint32_t aB = smem_u32(Asm);
    const uint32_t bB = smem_u32(Bsm);

    const int tid  = threadIdx.x;
    const int lane = tid & 31;
    const int wid  = tid >> 5;
    const int wm   = wid & 3;              // 4 x 32 m
    const int wn   = wid >> 2;             // 4 x 64 n

    const int c  = blockIdx.x;
    int u        = (int)(((long long)UNITS_TOTAL * c) / GRID_G);
    const int u1 = (int)(((long long)UNITS_TOTAL * (c + 1)) / GRID_G);

    // cp.async per-thread chunk coordinates (2 chunks each for A and B)
    // A: p -> m = p>>3, kq = (p&7)*4 (floats).  B: p -> n = p>>2, k8 = (p&3)*8 (halves)
#define ISSUE(Abase, kt, slot)                                                \
    {                                                                         \
        const int k0 = (kt) * BK;                                             \
        _Pragma("unroll")                                                     \
        for (int i = 0; i < 2; i++) {                                         \
            int p = tid + i * NTHREADS;                                       \
            int m = p >> 3, kq = (p & 7) * 4;                                 \
            CP16(aB + (slot) * A_ST_BYTES + (m * RSA + kq) * 4,               \
                 (Abase) + (size_t)m * FF + k0 + kq);                         \
        }                                                                     \
        _Pragma("unroll")                                                     \
        for (int i = 0; i < 2; i++) {                                         \
            int p = tid + i * NTHREADS;                                       \
            int n = p >> 2, k8 = (p & 3) * 8;                                 \
            CP16(bB + (slot) * B_ST_BYTES + (n * RSB + k8) * 2,               \
                 g_Bth + (size_t)n * FF + k0 + k8);                           \
        }                                                                     \
    }

    while (u < u1) {
        const int tile = u / KUNITS;
        const int kbeg = u - tile * KUNITS;
        const int seg  = min(KUNITS - kbeg, u1 - u);
        const int kend = kbeg + seg;
        const int row0 = tile * BM;
        const float* Abase = hmat + (size_t)row0 * FF;

        // prologue: 3 stages in flight
#pragma unroll
        for (int s = 0; s < 3; s++) {
            if (s < seg) ISSUE(Abase, kbeg + s, s);
            CP_COMMIT();
        }

        float acc[2][8][4];
#pragma unroll
        for (int i = 0; i < 2; i++)
#pragma unroll
            for (int j = 0; j < 8; j++)
#pragma unroll
                for (int q = 0; q < 4; q++) acc[i][j][q] = 0.f;

        for (int kt = kbeg; kt < kend; kt++) {
            const int slot = (kt - kbeg) & (NSTG - 1);
            CP_WAIT2();
            __syncthreads();
            if (kt + 3 < kend) ISSUE(Abase, kt + 3, (kt + 3 - kbeg) & (NSTG - 1));
            CP_COMMIT();

            const float*   Ab = Asm + slot * (BM * RSA);
            const uint32_t bS = bB + slot * B_ST_BYTES;
            const int mA = wm * 32 + (lane >> 2);
            const int r2 = (lane & 3) * 2;
            const int j8 = lane & 7;
            const int mi = lane >> 3;

#pragma unroll
            for (int ks = 0; ks < 2; ks++) {
                const int kb = ks * 16;
                unsigned a[2][4], b[8][2];
#pragma unroll
                for (int mt = 0; mt < 2; mt++) {
                    const int m = mA + mt * 16;
                    float2 f;
                    f = *(const float2*)(Ab + m * RSA + kb + r2);
                    a[mt][0] = packh2(f.x, f.y);
                    f = *(const float2*)(Ab + (m + 8) * RSA + kb + r2);
                    a[mt][1] = packh2(f.x, f.y);
                    f = *(const float2*)(Ab + m * RSA + kb + 8 + r2);
                    a[mt][2] = packh2(f.x, f.y);
                    f = *(const float2*)(Ab + (m + 8) * RSA + kb + 8 + r2);
                    a[mt][3] = packh2(f.x, f.y);
                }
#pragma unroll
                for (int pr = 0; pr < 4; pr++) {
                    const int n8 = wn * 64 + pr * 16;
                    uint32_t ad = bS +
                        ((n8 + (mi >> 1) * 8 + j8) * RSB + kb + (mi & 1) * 8) * 2;
                    asm volatile(
                        "ldmatrix.sync.aligned.m8n8.x4.shared.b16 {%0,%1,%2,%3}, [%4];"
                        : "=r"(b[2 * pr][0]), "=r"(b[2 * pr][1]),
                          "=r"(b[2 * pr + 1][0]), "=r"(b[2 * pr + 1][1])
                        : "r"(ad));
                }
#pragma unroll
                for (int mt = 0; mt < 2; mt++)
#pragma unroll
                    for (int nt = 0; nt < 8; nt++)
                        mma_f16(acc[mt][nt], a[mt], b[nt]);
            }
        }
        __syncthreads();   // protect slots before next segment's prologue

        // flush tile segment via atomicAdd
#pragma unroll
        for (int mt = 0; mt < 2; mt++) {
            int r = row0 + wm * 32 + mt * 16 + (lane >> 2);
#pragma unroll
            for (int nt = 0; nt < 8; nt++) {
                int cc = wn * 64 + nt * 8 + (lane & 3) * 2;
                atomicAdd(&g_Wh[(size_t)r * NT + cc],           acc[mt][nt][0]);
                atomicAdd(&g_Wh[(size_t)r * NT + cc + 1],       acc[mt][nt][1]);
                atomicAdd(&g_Wh[(size_t)(r + 8) * NT + cc],     acc[mt][nt][2]);
                atomicAdd(&g_Wh[(size_t)(r + 8) * NT + cc + 1], acc[mt][nt][3]);
            }
        }

        u += seg;
    }
#undef ISSUE
}

// ---------------------------------------------------------------------------
// Kernel B: GAT attention + ELU. grid (256,4), 256 threads, 5 blocks/SM.
// ---------------------------------------------------------------------------
#define NP 52
__global__ __launch_bounds__(256, 5)
void attn_kernel(const float* __restrict__ a, float* __restrict__ out)
{
    __shared__ float sWh[NP][68];
    __shared__ float sA2[NP][68];
    __shared__ float sE[NP][NP];
    __shared__ float sS1[NN];
    __shared__ unsigned char sAdj[NN * NN];

    const int b    = blockIdx.x;
    const int h    = blockIdx.y;
    const int tid  = threadIdx.x;
    const int lane = tid & 31;
    const int wid  = tid >> 5;

    {
        const unsigned* src = (const unsigned*)(g_adj + (size_t)b * NN * NN);
        unsigned* dst = (unsigned*)sAdj;
        for (int i = tid; i < NN * NN / 4; i += 256) dst[i] = src[i];
    }

    if (tid < 2 * 68) {
        int r = 50 + tid / 68, cidx = tid % 68;
        sWh[r][cidx] = 0.f;
        sA2[r][cidx] = 0.f;
    }

    for (int idx = tid; idx < NN * OO / 4; idx += 256) {
        int n_ = idx >> 4;
        int o4 = (idx & 15) * 4;
        float4 w  = *(const float4*)&g_Wh[(size_t)(b * NN + n_) * NT + h * OO + o4];
        float4 av = *(const float4*)&a[(size_t)(h * NN + n_) * (2 * OO) + OO + o4];
        *(float4*)&sWh[n_][o4] = w;
        *(float4*)&sA2[n_][o4] = av;
    }
    __syncthreads();

    for (int n_ = wid; n_ < NN; n_ += 8) {
        float a1v0 = a[(size_t)(h * NN + n_) * (2 * OO) + lane];
        float a1v1 = a[(size_t)(h * NN + n_) * (2 * OO) + lane + 32];
        float v = sWh[n_][lane] * a1v0 + sWh[n_][lane + 32] * a1v1;
#pragma unroll
        for (int off = 16; off; off >>= 1) v += __shfl_xor_sync(0xffffffffu, v, off);
        if (lane == 0) sS1[n_] = v;
    }

    if (tid < 169) {
        const int n0 = (tid / 13) * 4;
        const int m0 = (tid % 13) * 4;
        float acc[4][4];
#pragma unroll
        for (int i = 0; i < 4; i++)
#pragma unroll
            for (int j = 0; j < 4; j++) acc[i][j] = 0.f;
#pragma unroll 8
        for (int o = 0; o < OO; o++) {
            float av[4], wv[4];
#pragma unroll
            for (int i = 0; i < 4; i++) av[i] = sA2[n0 + i][o];
#pragma unroll
            for (int j = 0; j < 4; j++) wv[j] = sWh[m0 + j][o];
#pragma unroll
            for (int i = 0; i < 4; i++)
#pragma unroll
                for (int j = 0; j < 4; j++)
                    acc[i][j] = fmaf(av[i], wv[j], acc[i][j]);
        }
#pragma unroll
        for (int i = 0; i < 4; i++)
#pragma unroll
            for (int j = 0; j < 4; j++) sE[n0 + i][m0 + j] = acc[i][j];
    }
    __syncthreads();

    for (int n_ = wid; n_ < NN; n_ += 8) {
        float s1v = sS1[n_];
        int m0 = lane, m1 = lane + 32;
        float t0 = s1v + sE[n_][m0];
        t0 = (t0 >= 0.f) ? t0 : 0.2f * t0;
        float v0 = sAdj[n_ * NN + m0] ? t0 : -9e15f;
        float v1 = -9e15f;
        if (m1 < NN) {
            float t1 = s1v + sE[n_][m1];
            t1 = (t1 >= 0.f) ? t1 : 0.2f * t1;
            v1 = sAdj[n_ * NN + m1] ? t1 : -9e15f;
        }
        float mx = fmaxf(v0, v1);
#pragma unroll
        for (int off = 16; off; off >>= 1)
            mx = fmaxf(mx, __shfl_xor_sync(0xffffffffu, mx, off));
        float e0_ = __expf(v0 - mx);
        float e1_ = (m1 < NN) ? __expf(v1 - mx) : 0.f;
        float sum = e0_ + e1_;
#pragma unroll
        for (int off = 16; off; off >>= 1)
            sum += __shfl_xor_sync(0xffffffffu, sum, off);
        float inv = 1.f / sum;
        sE[n_][m0] = e0_ * inv;
        if (m1 < NN) sE[n_][m1] = e1_ * inv;
    }
    __syncthreads();

    if (tid < 208) {
        const int n0 = (tid / 16) * 4;
        const int o4 = (tid % 16) * 4;
        float4 acc[4];
#pragma unroll
        for (int i = 0; i < 4; i++) acc[i] = make_float4(0.f, 0.f, 0.f, 0.f);
#pragma unroll 5
        for (int m = 0; m < NN; m++) {
            float4 wv = *(const float4*)&sWh[m][o4];
#pragma unroll
            for (int i = 0; i < 4; i++) {
                float at = sE[n0 + i][m];
                acc[i].x = fmaf(at, wv.x, acc[i].x);
                acc[i].y = fmaf(at, wv.y, acc[i].y);
                acc[i].z = fmaf(at, wv.z, acc[i].z);
                acc[i].w = fmaf(at, wv.w, acc[i].w);
            }
        }
#pragma unroll
        for (int i = 0; i < 4; i++) {
            int n_ = n0 + i;
            if (n_ < NN) {
                float4 wv = *(const float4*)&sWh[n_][o4];
                float4 v = make_float4(acc[i].x + 0.3f * wv.x,
                                       acc[i].y + 0.3f * wv.y,
                                       acc[i].z + 0.3f * wv.z,
                                       acc[i].w + 0.3f * wv.w);
                v.x = (v.x > 0.f) ? v.x : expm1f(v.x);
                v.y = (v.y > 0.f) ? v.y : expm1f(v.y);
                v.z = (v.z > 0.f) ? v.z : expm1f(v.z);
                v.w = (v.w > 0.f) ? v.w : expm1f(v.w);
                *(float4*)&out[(size_t)(b * NN + n_) * NT + h * OO + o4] = v;
            }
        }
    }
}

// ---------------------------------------------------------------------------
extern "C" void kernel_launch(void* const* d_in, const int* in_sizes, int n_in,
                              void* d_out, int out_size)
{
    const float* h_    = (const float*)d_in[0];  // (B, N, F)
    const float* probs = (const float*)d_in[1];  // (B, N*N)
    const float* u_    = (const float*)d_in[2];  // (B, N*N, 2)
    const float* W_    = (const float*)d_in[3];  // (H, F, O)
    const float* a_    = (const float*)d_in[4];  // (H, N, 2*O)
    float* out = (float*)d_out;

    zero_kernel<<<592, 256>>>();
    adj_kernel<<<(BB * NN * NN + 255) / 256, 256>>>(probs, u_);

    dim3 tgrid(FF / 32, HH);
    wT_kernel<<<tgrid, 256>>>(W_);

    cudaFuncSetAttribute(gemm_f16, cudaFuncAttributeMaxDynamicSharedMemorySize,
                         SMEM_BYTES);
    gemm_f16<<<GRID_G, NTHREADS, SMEM_BYTES>>>(h_);

    dim3 agrid(BB, HH);
    attn_kernel<<<agrid, 256>>>(a_, out);
}